// round 12
// baseline (speedup 1.0000x reference)
#include <cuda_runtime.h>
#include <cuda_bf16.h>
#include <mma.h>
#include <stdint.h>
#include <math.h>

using namespace nvcuda;

#define BB 16
#define LC 1024
#define LQ 512
#define DD 512
#define NEG_INF_F (-1e30f)

typedef __nv_bfloat16 bf16;

// ======================= scratch (static device arrays) =====================
__device__ float g_c1[BB * LC];
__device__ float g_q2[BB * LQ];
__device__ float g_S [(size_t)BB * LC * LQ];   // logits
__device__ float g_S2[(size_t)BB * LC * LQ];   // col softmax fp32
__device__ float g_T [(size_t)BB * LQ * DD];   // S2^T C fp32

__device__ bf16 g_CWh[(size_t)BB * LC * DD], g_CWl[(size_t)BB * LC * DD];
__device__ bf16 g_Qh [(size_t)BB * LQ * DD], g_Ql [(size_t)BB * LQ * DD];
__device__ bf16 g_QTh[(size_t)BB * DD * LQ], g_QTl[(size_t)BB * DD * LQ];
__device__ bf16 g_CTh[(size_t)BB * DD * LC], g_CTl[(size_t)BB * DD * LC];
__device__ bf16 g_S1h[(size_t)BB * LC * LQ], g_S1l[(size_t)BB * LC * LQ];
__device__ bf16 g_S2Th[(size_t)BB * LQ * LC], g_S2Tl[(size_t)BB * LQ * LC];
__device__ bf16 g_TTh[(size_t)BB * DD * LQ], g_TTl[(size_t)BB * DD * LQ];
__device__ bf16 g_Wh [(size_t)DD * 4 * DD],  g_Wl [(size_t)DD * 4 * DD];
__device__ bf16 g_Xh [(size_t)BB * LC * 4 * DD], g_Xl[(size_t)BB * LC * 4 * DD];

// Device-side buffer resolution — NEVER pass __device__ symbols from host.
// ids: 0=CW 1=Q 2=QT 3=CT 4=S1 5=S2T 6=TT 7=W 8=X
__device__ __forceinline__ bf16* bufH(int i) {
    switch (i) {
        case 0: return g_CWh; case 1: return g_Qh;  case 2: return g_QTh;
        case 3: return g_CTh; case 4: return g_S1h; case 5: return g_S2Th;
        case 6: return g_TTh; case 7: return g_Wh;  default: return g_Xh;
    }
}
__device__ __forceinline__ bf16* bufL(int i) {
    switch (i) {
        case 0: return g_CWl; case 1: return g_Ql;  case 2: return g_QTl;
        case 3: return g_CTl; case 4: return g_S1l; case 5: return g_S2Tl;
        case 6: return g_TTl; case 7: return g_Wl;  default: return g_Xl;
    }
}

// ======================= helpers ============================================
__device__ __forceinline__ void bsplit(float x, bf16& h, bf16& l) {
    h = __float2bfloat16(x);
    l = __float2bfloat16(x - __bfloat162float(h));
}
#define CP_ASYNC(sa, ga) asm volatile( \
    "cp.async.cg.shared.global [%0], [%1], 16;" :: "r"(sa), "l"(ga))
#define CP_COMMIT() asm volatile("cp.async.commit_group;" ::: "memory")
#define CP_WAIT(n) asm volatile("cp.async.wait_group %0;" :: "n"(n) : "memory")
__device__ __forceinline__ uint32_t smem_u32(const void* p) {
    uint32_t a;
    asm("{ .reg .u64 t; cvta.to.shared.u64 t, %1; cvt.u32.u64 %0, t; }"
        : "=r"(a) : "l"(p));
    return a;
}

// ======================= small kernels ======================================
__global__ void rowdot_kernel(const float* __restrict__ X, const float* __restrict__ w,
                              int which, int nrows) {
    float* out = which ? g_q2 : g_c1;
    int gw = (blockIdx.x * blockDim.x + threadIdx.x) >> 5;
    int lane = threadIdx.x & 31;
    if (gw >= nrows) return;
    const float* row = X + (size_t)gw * DD;
    float s = 0.f;
#pragma unroll 4
    for (int k = lane; k < DD; k += 32) s = fmaf(row[k], w[k], s);
#pragma unroll
    for (int o = 16; o; o >>= 1) s += __shfl_xor_sync(0xffffffffu, s, o);
    if (lane == 0) out[gw] = s;
}

__device__ __forceinline__ void split2_store(bf16* h, bf16* l, size_t idx,
                                             float a, float b) {
    bf16 h0, l0, h1, l1;
    bsplit(a, h0, l0);
    bsplit(b, h1, l1);
    *(__nv_bfloat162*)(h + idx) = __halves2bfloat162(h0, h1);
    *(__nv_bfloat162*)(l + idx) = __halves2bfloat162(l0, l1);
}

// C: one read -> CW (scaled) split AND X[:,0:512] split
__global__ void split_c_kernel(const float* __restrict__ C, const float* __restrict__ w3) {
    size_t i = ((size_t)blockIdx.x * blockDim.x + threadIdx.x) * 4;  // < BB*LC*DD
    size_t row = i >> 9;
    int c = (int)(i & (DD - 1));
    float4 v = *(const float4*)(C + i);
    float4 s = *(const float4*)(w3 + c);
    split2_store(g_Xh, g_Xl, row * (4 * DD) + c, v.x, v.y);
    split2_store(g_Xh, g_Xl, row * (4 * DD) + c + 2, v.z, v.w);
    split2_store(g_CWh, g_CWl, i, v.x * s.x, v.y * s.y);
    split2_store(g_CWh, g_CWl, i + 2, v.z * s.z, v.w * s.w);
}

__global__ void split4_kernel(const float* __restrict__ src, int dstIdx, size_t n) {
    size_t i = ((size_t)blockIdx.x * blockDim.x + threadIdx.x) * 4;
    if (i >= n) return;
    float4 v = *(const float4*)(src + i);
    bf16* h = bufH(dstIdx);
    bf16* l = bufL(dstIdx);
    split2_store(h, l, i, v.x, v.y);
    split2_store(h, l, i + 2, v.z, v.w);
}

// src fp32 [R x Cc] per batch -> dst bf16 hi/lo [Cc x R]
// srcSel: 0 = srcParam (harness ptr), 1 = g_S2, 2 = g_T
__global__ void transpose_split_kernel(const float* __restrict__ srcParam, int srcSel,
                                       int dstIdx, int R, int Cc) {
    __shared__ float t[32][33];
    const float* src = (srcSel == 0) ? srcParam : (srcSel == 1 ? g_S2 : g_T);
    bf16* h = bufH(dstIdx);
    bf16* l = bufL(dstIdx);
    int b = blockIdx.z;
    const float* S = src + (size_t)b * R * Cc;
    size_t ob = (size_t)b * R * Cc;
    int c0 = blockIdx.x * 32, r0 = blockIdx.y * 32;
    int tx = threadIdx.x, ty = threadIdx.y;
#pragma unroll
    for (int j = 0; j < 32; j += 8)
        t[ty + j][tx] = S[(size_t)(r0 + ty + j) * Cc + c0 + tx];
    __syncthreads();
#pragma unroll
    for (int j = 0; j < 32; j += 8) {
        float v = t[tx][ty + j];
        size_t o = ob + (size_t)(c0 + ty + j) * R + r0 + tx;
        bf16 hh, ll;
        bsplit(v, hh, ll);
        h[o] = hh;
        l[o] = ll;
    }
}

__global__ void softmax_row_kernel(const float* __restrict__ qmask) {
    __shared__ float sred[64];
    int i = blockIdx.x, b = blockIdx.y;
    int t = threadIdx.x;
    size_t base = ((size_t)b * LC + i) * LQ;
    const float* srow = g_S + base;
    float m0 = qmask[b * LQ + t], m1 = qmask[b * LQ + t + 256];
    float x0 = srow[t] * m0 + (1.f - m0) * NEG_INF_F;
    float x1 = srow[t + 256] * m1 + (1.f - m1) * NEG_INF_F;
    float v = fmaxf(x0, x1);
    int lane = t & 31, wid = t >> 5;
#pragma unroll
    for (int o = 16; o; o >>= 1) v = fmaxf(v, __shfl_xor_sync(0xffffffffu, v, o));
    if (lane == 0) sred[wid] = v;
    __syncthreads();
    if (t < 32) {
        float w2 = (t < 8) ? sred[t] : -3e38f;
#pragma unroll
        for (int o = 4; o; o >>= 1) w2 = fmaxf(w2, __shfl_xor_sync(0xffffffffu, w2, o));
        if (t == 0) sred[32] = w2;
    }
    __syncthreads();
    float mx = sred[32];
    float e0 = __expf(x0 - mx), e1 = __expf(x1 - mx);
    v = e0 + e1;
#pragma unroll
    for (int o = 16; o; o >>= 1) v += __shfl_xor_sync(0xffffffffu, v, o);
    if (lane == 0) sred[wid] = v;
    __syncthreads();
    if (t < 32) {
        float w2 = (t < 8) ? sred[t] : 0.f;
#pragma unroll
        for (int o = 4; o; o >>= 1) w2 += __shfl_xor_sync(0xffffffffu, w2, o);
        if (t == 0) sred[33] = w2;
    }
    __syncthreads();
    float inv = 1.f / sred[33];
    bsplit(e0 * inv, g_S1h[base + t], g_S1l[base + t]);
    bsplit(e1 * inv, g_S1h[base + t + 256], g_S1l[base + t + 256]);
}

__global__ void softmax_col_kernel(const float* __restrict__ cmask) {
    int j = blockIdx.x * blockDim.x + threadIdx.x;
    int b = blockIdx.y;
    const float* Sb = g_S + (size_t)b * LC * LQ;
    float* Ob = g_S2 + (size_t)b * LC * LQ;
    const float* cm = cmask + b * LC;
    float m = -3e38f, l = 0.f;
    for (int i = 0; i < LC; i++) {
        float cmi = cm[i];
        float x = Sb[(size_t)i * LQ + j] * cmi + (1.f - cmi) * NEG_INF_F;
        float nm = fmaxf(m, x);
        l = l * __expf(m - nm) + __expf(x - nm);
        m = nm;
    }
    float inv = 1.f / l;
    for (int i = 0; i < LC; i++) {
        float cmi = cm[i];
        float x = Sb[(size_t)i * LQ + j] * cmi + (1.f - cmi) * NEG_INF_F;
        Ob[(size_t)i * LQ + j] = __expf(x - m) * inv;
    }
}

// ======================= WMMA GEMM (128x256 tile, 2-stage cp.async) =========
// D[128x256] per CTA; A,B bf16 hi/lo K-major [rows x K] row-major.
// bf16x3: D = Ah*Bh + Ah*Bl + Al*Bh, fp32 accumulate (wmma).
#define KC 32
#define LDT 40                          // padded smem row stride (80 B)
#define PADB 80
#define ATILE (128 * PADB)              // 10240 B
#define BTILE (256 * PADB)              // 20480 B
#define STAGEB (2 * ATILE + 2 * BTILE)  // 61440 B: Ah, Al, Bh, Bl
#define SMEM_GEMM (2 * STAGEB)          // 122880 B double-buffered

__device__ __forceinline__ void epi_pair(int mode, int b, int row, int col,
                                         float v0, float v1, float* outF,
                                         const float* Csrc, const float* bias) {
    if (mode == 0) {  // S logits += c1[row] + q2[col]
        size_t grow = (size_t)b * LC + row;
        float c1v = g_c1[b * LC + row];
        float2 o = make_float2(v0 + c1v + g_q2[b * LQ + col],
                               v1 + c1v + g_q2[b * LQ + col + 1]);
        *(float2*)(g_S + grow * LQ + col) = o;
    } else if (mode == 1) {  // plain fp32 (T)
        *(float2*)(g_T + ((size_t)b * LQ + row) * DD + col) = make_float2(v0, v1);
    } else if (mode == 2 || mode == 3) {  // X features
        size_t grow = (size_t)b * LC + row;
        const float* crow = Csrc + grow * DD + col;
        size_t xrow = grow * (size_t)(4 * DD);
        bf16 h0, l0, h1, l1;
        if (mode == 2) {
            bsplit(v0, h0, l0);
            bsplit(v1, h1, l1);
            *(__nv_bfloat162*)(g_Xh + xrow + DD + col) = __halves2bfloat162(h0, h1);
            *(__nv_bfloat162*)(g_Xl + xrow + DD + col) = __halves2bfloat162(l0, l1);
        }
        int off = (mode == 2) ? 2 * DD : 3 * DD;
        bsplit(crow[0] * v0, h0, l0);
        bsplit(crow[1] * v1, h1, l1);
        *(__nv_bfloat162*)(g_Xh + xrow + off + col) = __halves2bfloat162(h0, h1);
        *(__nv_bfloat162*)(g_Xl + xrow + off + col) = __halves2bfloat162(l0, l1);
    } else {  // mode 4: final + bias (row is global over BB*LC; outF = harness out)
        *(float2*)(outF + (size_t)row * DD + col) =
            make_float2(v0 + bias[col], v1 + bias[col + 1]);
    }
}

__global__ void __launch_bounds__(256)
wmma_gemm(int aIdx, int bIdx, size_t aStride, size_t bStride, int K, int mode,
          float* __restrict__ outH,
          const float* __restrict__ Csrc, const float* __restrict__ bias) {
    extern __shared__ __align__(16) char dsm[];
    int tid = threadIdx.x, lane = tid & 31, wid = tid >> 5;
    int warp_m = wid & 1, warp_n = wid >> 1;  // 2 x 4 warps; warp tile 64 x 64
    int b = blockIdx.z;
    int row0 = blockIdx.y << 7, col0 = blockIdx.x << 8;

    const bf16* baseA[2];
    const bf16* baseB[2];
    baseA[0] = bufH(aIdx) + (size_t)b * aStride + (size_t)row0 * K;
    baseA[1] = bufL(aIdx) + (size_t)b * aStride + (size_t)row0 * K;
    baseB[0] = bufH(bIdx) + (size_t)b * bStride + (size_t)col0 * K;
    baseB[1] = bufL(bIdx) + (size_t)b * bStride + (size_t)col0 * K;

    uint32_t sb = smem_u32(dsm);
    wmma::fragment<wmma::accumulator, 16, 16, 16, float> acc[4][4];
#pragma unroll
    for (int mi = 0; mi < 4; mi++)
#pragma unroll
        for (int nj = 0; nj < 4; nj++) wmma::fill_fragment(acc[mi][nj], 0.0f);

    const int KT = K / KC;
    int lrow = tid >> 1;           // 0..127
    int lcc0 = (tid & 1) << 1;     // chunk index {0,2}

#define ISSUE(kt, st) do {                                                     \
        int _k0 = (kt) * KC;                                                   \
        uint32_t _s0 = sb + (st) * STAGEB;                                     \
        _Pragma("unroll")                                                      \
        for (int m = 0; m < 2; m++) {                                          \
            const bf16* _g = baseA[m] + (size_t)lrow * K + _k0;                \
            uint32_t _sm = _s0 + m * ATILE + lrow * PADB;                      \
            CP_ASYNC(_sm + lcc0 * 16, _g + lcc0 * 8);                          \
            CP_ASYNC(_sm + (lcc0 + 1) * 16, _g + (lcc0 + 1) * 8);              \
        }                                                                      \
        _Pragma("unroll")                                                      \
        for (int m = 0; m < 2; m++) {                                          \
            _Pragma("unroll")                                                  \
            for (int rh = 0; rh < 2; rh++) {                                   \
                int _row = lrow + rh * 128;                                    \
                const bf16* _g = baseB[m] + (size_t)_row * K + _k0;            \
                uint32_t _sm = _s0 + 2 * ATILE + m * BTILE + _row * PADB;      \
                CP_ASYNC(_sm + lcc0 * 16, _g + lcc0 * 8);                      \
                CP_ASYNC(_sm + (lcc0 + 1) * 16, _g + (lcc0 + 1) * 8);          \
            }                                                                  \
        }                                                                      \
        CP_COMMIT();                                                           \
    } while (0)

    ISSUE(0, 0);

    for (int kt = 0; kt < KT; kt++) {
        int st = kt & 1;
        if (kt + 1 < KT) {
            ISSUE(kt + 1, st ^ 1);
            CP_WAIT(1);
        } else {
            CP_WAIT(0);
        }
        __syncthreads();  // cp.async data visible to all warps

        const bf16* sAh = (const bf16*)(dsm + st * STAGEB);
        const bf16* sAl = (const bf16*)(dsm + st * STAGEB + ATILE);
        const bf16* sBh = (const bf16*)(dsm + st * STAGEB + 2 * ATILE);
        const bf16* sBl = (const bf16*)(dsm + st * STAGEB + 2 * ATILE + BTILE);

#pragma unroll
        for (int ks = 0; ks < KC; ks += 16) {
            wmma::fragment<wmma::matrix_b, 16, 16, 16, bf16, wmma::col_major> fbh[4], fbl[4];
#pragma unroll
            for (int nj = 0; nj < 4; nj++) {
                int nrow = warp_n * 64 + nj * 16;
                wmma::load_matrix_sync(fbh[nj], sBh + nrow * LDT + ks, LDT);
                wmma::load_matrix_sync(fbl[nj], sBl + nrow * LDT + ks, LDT);
            }
#pragma unroll
            for (int mi = 0; mi < 4; mi++) {
                int arow = warp_m * 64 + mi * 16;
                wmma::fragment<wmma::matrix_a, 16, 16, 16, bf16, wmma::row_major> fah, fal;
                wmma::load_matrix_sync(fah, sAh + arow * LDT + ks, LDT);
                wmma::load_matrix_sync(fal, sAl + arow * LDT + ks, LDT);
#pragma unroll
                for (int nj = 0; nj < 4; nj++) {
                    wmma::mma_sync(acc[mi][nj], fah, fbh[nj], acc[mi][nj]);
                    wmma::mma_sync(acc[mi][nj], fah, fbl[nj], acc[mi][nj]);
                    wmma::mma_sync(acc[mi][nj], fal, fbh[nj], acc[mi][nj]);
                }
            }
        }
        __syncthreads();  // compute done before next ISSUE overwrites this stage
    }

    // ---- epilogue: stage each 16x16 acc tile through smem ----
    float* stag = reinterpret_cast<float*>(dsm) + wid * 256;  // 1KB per warp
    int prow = lane >> 1, pc0 = (lane & 1) << 3;
#pragma unroll
    for (int mi = 0; mi < 4; mi++)
#pragma unroll
        for (int nj = 0; nj < 4; nj++) {
            wmma::store_matrix_sync(stag, acc[mi][nj], 16, wmma::mem_row_major);
            __syncwarp();
            int rr = row0 + warp_m * 64 + mi * 16 + prow;
            int cc0 = col0 + warp_n * 64 + nj * 16 + pc0;
#pragma unroll
            for (int p = 0; p < 8; p += 2)
                epi_pair(mode, b, rr, cc0 + p,
                         stag[prow * 16 + pc0 + p], stag[prow * 16 + pc0 + p + 1],
                         outH, Csrc, bias);
            __syncwarp();
        }
}

// ======================= launch =============================================
extern "C" void kernel_launch(void* const* d_in, const int* in_sizes, int n_in,
                              void* d_out, int out_size) {
    const float* C     = (const float*)d_in[0];
    const float* Q     = (const float*)d_in[1];
    const float* cmask = (const float*)d_in[2];
    const float* qmask = (const float*)d_in[3];
    const float* w     = (const float*)d_in[4];
    const float* out_w = (const float*)d_in[5];
    const float* out_b = (const float*)d_in[6];
    float* out         = (float*)d_out;

    static int smem_set = 0;
    if (!smem_set) {
        cudaFuncSetAttribute(wmma_gemm, cudaFuncAttributeMaxDynamicSharedMemorySize,
                             SMEM_GEMM);
        smem_set = 1;
    }

    // row dots
    rowdot_kernel<<<(BB * LC) / 8, 256>>>(C, w, 0, BB * LC);
    rowdot_kernel<<<(BB * LQ) / 8, 256>>>(Q, w + DD, 1, BB * LQ);

    // operand prep (bf16 splits + transposes)
    {
        size_t n = (size_t)BB * LC * DD;           // 8388608
        split_c_kernel<<<(unsigned)(n / 1024), 256>>>(C, w + 2 * DD);
    }
    {
        size_t n = (size_t)BB * LQ * DD;
        split4_kernel<<<(unsigned)(n / 1024), 256>>>(Q, 1 /*Q*/, n);
    }
    {
        size_t n = (size_t)DD * 4 * DD;
        split4_kernel<<<(unsigned)(n / 1024), 256>>>(out_w, 7 /*W*/, n);
    }
    transpose_split_kernel<<<dim3(DD / 32, LQ / 32, BB), dim3(32, 8)>>>(Q, 0, 2 /*QT*/, LQ, DD);
    transpose_split_kernel<<<dim3(DD / 32, LC / 32, BB), dim3(32, 8)>>>(C, 0, 3 /*CT*/, LC, DD);

    // S = (C*w3) @ Q^T + c1 + q2
    wmma_gemm<<<dim3(LQ / 256, LC / 128, BB), 256, SMEM_GEMM>>>(
        0 /*CW*/, 1 /*Q*/, (size_t)LC * DD, (size_t)LQ * DD, DD, 0, nullptr, nullptr, nullptr);

    // softmaxes
    softmax_row_kernel<<<dim3(LC, BB), 256>>>(qmask);        // -> S1 bf16 hi/lo
    softmax_col_kernel<<<dim3(LQ / 256, BB), 256>>>(cmask);  // -> g_S2 fp32
    transpose_split_kernel<<<dim3(LQ / 32, LC / 32, BB), dim3(32, 8)>>>(nullptr, 1 /*g_S2*/, 5 /*S2T*/, LC, LQ);

    // T = S2^T @ C   (A = S2T [LQ x LC], B = CT [DD x LC])
    wmma_gemm<<<dim3(DD / 256, LQ / 128, BB), 256, SMEM_GEMM>>>(
        5 /*S2T*/, 3 /*CT*/, (size_t)LQ * LC, (size_t)DD * LC, LC, 1, nullptr, nullptr, nullptr);
    transpose_split_kernel<<<dim3(DD / 32, LQ / 32, BB), dim3(32, 8)>>>(nullptr, 2 /*g_T*/, 6 /*TT*/, LQ, DD);

    // A = S1 @ Q  -> X[:,512:1024] and C*A -> X[:,1024:1536]
    wmma_gemm<<<dim3(DD / 256, LC / 128, BB), 256, SMEM_GEMM>>>(
        4 /*S1*/, 2 /*QT*/, (size_t)LC * LQ, (size_t)DD * LQ, LQ, 2, nullptr, C, nullptr);

    // Bm = S1 @ T -> C*Bm -> X[:,1536:2048]
    wmma_gemm<<<dim3(DD / 256, LC / 128, BB), 256, SMEM_GEMM>>>(
        4 /*S1*/, 6 /*TT*/, (size_t)LC * LQ, (size_t)DD * LQ, LQ, 3, nullptr, C, nullptr);

    // out = X @ out_w^T + out_b   (M = BB*LC, N = DD, K = 4*DD)
    wmma_gemm<<<dim3(DD / 256, (BB * LC) / 128, 1), 256, SMEM_GEMM>>>(
        8 /*X*/, 7 /*W*/, 0, 0, 4 * DD, 4, out, nullptr, out_b);
}

// round 13
// speedup vs baseline: 1.3987x; 1.3987x over previous
#include <cuda_runtime.h>
#include <cuda_bf16.h>
#include <mma.h>
#include <stdint.h>
#include <math.h>

using namespace nvcuda;

#define BB 16
#define LC 1024
#define LQ 512
#define DD 512
#define NEG_INF_F (-1e30f)

typedef __nv_bfloat16 bf16;

// ======================= scratch (static device arrays) =====================
__device__ float g_c1[BB * LC];
__device__ float g_q2[BB * LQ];
__device__ float g_S [(size_t)BB * LC * LQ];   // logits
__device__ float g_S2[(size_t)BB * LC * LQ];   // col softmax fp32
__device__ float g_T [(size_t)BB * LQ * DD];   // S2^T C fp32

__device__ bf16 g_CWh[(size_t)BB * LC * DD], g_CWl[(size_t)BB * LC * DD];
__device__ bf16 g_Qh [(size_t)BB * LQ * DD], g_Ql [(size_t)BB * LQ * DD];
__device__ bf16 g_QTh[(size_t)BB * DD * LQ], g_QTl[(size_t)BB * DD * LQ];
__device__ bf16 g_CTh[(size_t)BB * DD * LC], g_CTl[(size_t)BB * DD * LC];
__device__ bf16 g_S1h[(size_t)BB * LC * LQ], g_S1l[(size_t)BB * LC * LQ];
__device__ bf16 g_S2Th[(size_t)BB * LQ * LC], g_S2Tl[(size_t)BB * LQ * LC];
__device__ bf16 g_TTh[(size_t)BB * DD * LQ], g_TTl[(size_t)BB * DD * LQ];
__device__ bf16 g_Wh [(size_t)DD * 4 * DD],  g_Wl [(size_t)DD * 4 * DD];
__device__ bf16 g_Xh [(size_t)BB * LC * 4 * DD], g_Xl[(size_t)BB * LC * 4 * DD];

// Device-side buffer resolution — NEVER pass __device__ symbols from host.
// ids: 0=CW 1=Q 2=QT 3=CT 4=S1 5=S2T 6=TT 7=W 8=X
__device__ __forceinline__ bf16* bufH(int i) {
    switch (i) {
        case 0: return g_CWh; case 1: return g_Qh;  case 2: return g_QTh;
        case 3: return g_CTh; case 4: return g_S1h; case 5: return g_S2Th;
        case 6: return g_TTh; case 7: return g_Wh;  default: return g_Xh;
    }
}
__device__ __forceinline__ bf16* bufL(int i) {
    switch (i) {
        case 0: return g_CWl; case 1: return g_Ql;  case 2: return g_QTl;
        case 3: return g_CTl; case 4: return g_S1l; case 5: return g_S2Tl;
        case 6: return g_TTl; case 7: return g_Wl;  default: return g_Xl;
    }
}

// ======================= helpers ============================================
__device__ __forceinline__ void bsplit(float x, bf16& h, bf16& l) {
    h = __float2bfloat16(x);
    l = __float2bfloat16(x - __bfloat162float(h));
}
#define CP_ASYNC(sa, ga) asm volatile( \
    "cp.async.cg.shared.global [%0], [%1], 16;" :: "r"(sa), "l"(ga))
#define CP_COMMIT() asm volatile("cp.async.commit_group;" ::: "memory")
#define CP_WAIT(n) asm volatile("cp.async.wait_group %0;" :: "n"(n) : "memory")
__device__ __forceinline__ uint32_t smem_u32(const void* p) {
    uint32_t a;
    asm("{ .reg .u64 t; cvta.to.shared.u64 t, %1; cvt.u32.u64 %0, t; }"
        : "=r"(a) : "l"(p));
    return a;
}

// ======================= small kernels ======================================
__global__ void rowdot_kernel(const float* __restrict__ X, const float* __restrict__ w,
                              int which, int nrows) {
    float* out = which ? g_q2 : g_c1;
    int gw = (blockIdx.x * blockDim.x + threadIdx.x) >> 5;
    int lane = threadIdx.x & 31;
    if (gw >= nrows) return;
    const float* row = X + (size_t)gw * DD;
    float s = 0.f;
#pragma unroll 4
    for (int k = lane; k < DD; k += 32) s = fmaf(row[k], w[k], s);
#pragma unroll
    for (int o = 16; o; o >>= 1) s += __shfl_xor_sync(0xffffffffu, s, o);
    if (lane == 0) out[gw] = s;
}

__device__ __forceinline__ void split2_store(bf16* h, bf16* l, size_t idx,
                                             float a, float b) {
    bf16 h0, l0, h1, l1;
    bsplit(a, h0, l0);
    bsplit(b, h1, l1);
    *(__nv_bfloat162*)(h + idx) = __halves2bfloat162(h0, h1);
    *(__nv_bfloat162*)(l + idx) = __halves2bfloat162(l0, l1);
}

// C: one read -> CW (scaled) split AND X[:,0:512] split
__global__ void split_c_kernel(const float* __restrict__ C, const float* __restrict__ w3) {
    size_t i = ((size_t)blockIdx.x * blockDim.x + threadIdx.x) * 4;  // < BB*LC*DD
    size_t row = i >> 9;
    int c = (int)(i & (DD - 1));
    float4 v = *(const float4*)(C + i);
    float4 s = *(const float4*)(w3 + c);
    split2_store(g_Xh, g_Xl, row * (4 * DD) + c, v.x, v.y);
    split2_store(g_Xh, g_Xl, row * (4 * DD) + c + 2, v.z, v.w);
    split2_store(g_CWh, g_CWl, i, v.x * s.x, v.y * s.y);
    split2_store(g_CWh, g_CWl, i + 2, v.z * s.z, v.w * s.w);
}

__global__ void split4_kernel(const float* __restrict__ src, int dstIdx, size_t n) {
    size_t i = ((size_t)blockIdx.x * blockDim.x + threadIdx.x) * 4;
    if (i >= n) return;
    float4 v = *(const float4*)(src + i);
    bf16* h = bufH(dstIdx);
    bf16* l = bufL(dstIdx);
    split2_store(h, l, i, v.x, v.y);
    split2_store(h, l, i + 2, v.z, v.w);
}

// src fp32 [R x Cc] per batch -> dst bf16 hi/lo [Cc x R]
// srcSel: 0 = srcParam (harness ptr), 1 = g_S2, 2 = g_T
__global__ void transpose_split_kernel(const float* __restrict__ srcParam, int srcSel,
                                       int dstIdx, int R, int Cc) {
    __shared__ float t[32][33];
    const float* src = (srcSel == 0) ? srcParam : (srcSel == 1 ? g_S2 : g_T);
    bf16* h = bufH(dstIdx);
    bf16* l = bufL(dstIdx);
    int b = blockIdx.z;
    const float* S = src + (size_t)b * R * Cc;
    size_t ob = (size_t)b * R * Cc;
    int c0 = blockIdx.x * 32, r0 = blockIdx.y * 32;
    int tx = threadIdx.x, ty = threadIdx.y;
#pragma unroll
    for (int j = 0; j < 32; j += 8)
        t[ty + j][tx] = S[(size_t)(r0 + ty + j) * Cc + c0 + tx];
    __syncthreads();
#pragma unroll
    for (int j = 0; j < 32; j += 8) {
        float v = t[tx][ty + j];
        size_t o = ob + (size_t)(c0 + ty + j) * R + r0 + tx;
        bf16 hh, ll;
        bsplit(v, hh, ll);
        h[o] = hh;
        l[o] = ll;
    }
}

__global__ void softmax_row_kernel(const float* __restrict__ qmask) {
    __shared__ float sred[64];
    int i = blockIdx.x, b = blockIdx.y;
    int t = threadIdx.x;
    size_t base = ((size_t)b * LC + i) * LQ;
    const float* srow = g_S + base;
    float m0 = qmask[b * LQ + t], m1 = qmask[b * LQ + t + 256];
    float x0 = srow[t] * m0 + (1.f - m0) * NEG_INF_F;
    float x1 = srow[t + 256] * m1 + (1.f - m1) * NEG_INF_F;
    float v = fmaxf(x0, x1);
    int lane = t & 31, wid = t >> 5;
#pragma unroll
    for (int o = 16; o; o >>= 1) v = fmaxf(v, __shfl_xor_sync(0xffffffffu, v, o));
    if (lane == 0) sred[wid] = v;
    __syncthreads();
    if (t < 32) {
        float w2 = (t < 8) ? sred[t] : -3e38f;
#pragma unroll
        for (int o = 4; o; o >>= 1) w2 = fmaxf(w2, __shfl_xor_sync(0xffffffffu, w2, o));
        if (t == 0) sred[32] = w2;
    }
    __syncthreads();
    float mx = sred[32];
    float e0 = __expf(x0 - mx), e1 = __expf(x1 - mx);
    v = e0 + e1;
#pragma unroll
    for (int o = 16; o; o >>= 1) v += __shfl_xor_sync(0xffffffffu, v, o);
    if (lane == 0) sred[wid] = v;
    __syncthreads();
    if (t < 32) {
        float w2 = (t < 8) ? sred[t] : 0.f;
#pragma unroll
        for (int o = 4; o; o >>= 1) w2 += __shfl_xor_sync(0xffffffffu, w2, o);
        if (t == 0) sred[33] = w2;
    }
    __syncthreads();
    float inv = 1.f / sred[33];
    bsplit(e0 * inv, g_S1h[base + t], g_S1l[base + t]);
    bsplit(e1 * inv, g_S1h[base + t + 256], g_S1l[base + t + 256]);
}

__global__ void softmax_col_kernel(const float* __restrict__ cmask) {
    int j = blockIdx.x * blockDim.x + threadIdx.x;
    int b = blockIdx.y;
    const float* Sb = g_S + (size_t)b * LC * LQ;
    float* Ob = g_S2 + (size_t)b * LC * LQ;
    const float* cm = cmask + b * LC;
    float m = -3e38f, l = 0.f;
    for (int i = 0; i < LC; i++) {
        float cmi = cm[i];
        float x = Sb[(size_t)i * LQ + j] * cmi + (1.f - cmi) * NEG_INF_F;
        float nm = fmaxf(m, x);
        l = l * __expf(m - nm) + __expf(x - nm);
        m = nm;
    }
    float inv = 1.f / l;
    for (int i = 0; i < LC; i++) {
        float cmi = cm[i];
        float x = Sb[(size_t)i * LQ + j] * cmi + (1.f - cmi) * NEG_INF_F;
        Ob[(size_t)i * LQ + j] = __expf(x - m) * inv;
    }
}

// ======================= WMMA GEMM (128x128, 3-stage, chain-broken) =========
// D[128x128] per CTA; A,B bf16 hi/lo K-major [rows x K] row-major.
// bf16x3: D = Ah*Bh + Ah*Bl + Al*Bh, fp32 accumulate (wmma).
#define KC 32
#define LDT 40                         // padded smem row stride (80 B)
#define PADB 80
#define TILEB (128 * PADB)             // 10240 B per matrix tile
#define STAGEB (4 * TILEB)             // Ah, Al, Bh, Bl = 40960 B
#define NSTAGE 3
#define SMEM_GEMM (NSTAGE * STAGEB)    // 122880 B

__device__ __forceinline__ void epi_pair(int mode, int b, int row, int col,
                                         float v0, float v1, float* outF,
                                         const float* Csrc, const float* bias) {
    if (mode == 0) {  // S logits += c1[row] + q2[col]
        size_t grow = (size_t)b * LC + row;
        float c1v = g_c1[b * LC + row];
        float2 o = make_float2(v0 + c1v + g_q2[b * LQ + col],
                               v1 + c1v + g_q2[b * LQ + col + 1]);
        *(float2*)(g_S + grow * LQ + col) = o;
    } else if (mode == 1) {  // plain fp32 (T)
        *(float2*)(g_T + ((size_t)b * LQ + row) * DD + col) = make_float2(v0, v1);
    } else if (mode == 2 || mode == 3) {  // X features
        size_t grow = (size_t)b * LC + row;
        const float* crow = Csrc + grow * DD + col;
        size_t xrow = grow * (size_t)(4 * DD);
        bf16 h0, l0, h1, l1;
        if (mode == 2) {
            bsplit(v0, h0, l0);
            bsplit(v1, h1, l1);
            *(__nv_bfloat162*)(g_Xh + xrow + DD + col) = __halves2bfloat162(h0, h1);
            *(__nv_bfloat162*)(g_Xl + xrow + DD + col) = __halves2bfloat162(l0, l1);
        }
        int off = (mode == 2) ? 2 * DD : 3 * DD;
        bsplit(crow[0] * v0, h0, l0);
        bsplit(crow[1] * v1, h1, l1);
        *(__nv_bfloat162*)(g_Xh + xrow + off + col) = __halves2bfloat162(h0, h1);
        *(__nv_bfloat162*)(g_Xl + xrow + off + col) = __halves2bfloat162(l0, l1);
    } else {  // mode 4: final + bias (row is global over BB*LC; outF = harness out)
        *(float2*)(outF + (size_t)row * DD + col) =
            make_float2(v0 + bias[col], v1 + bias[col + 1]);
    }
}

__global__ void __launch_bounds__(256)
wmma_gemm(int aIdx, int bIdx, size_t aStride, size_t bStride, int K, int mode,
          float* __restrict__ outH,
          const float* __restrict__ Csrc, const float* __restrict__ bias) {
    extern __shared__ __align__(16) char dsm[];
    int tid = threadIdx.x, lane = tid & 31, wid = tid >> 5;
    int warp_m = wid & 1, warp_n = wid >> 1;  // 2 x 4 warps; warp tile 64 x 32
    int b = blockIdx.z;
    int row0 = blockIdx.y << 7, col0 = blockIdx.x << 7;

    const bf16* base[4];
    base[0] = bufH(aIdx) + (size_t)b * aStride + (size_t)row0 * K;
    base[1] = bufL(aIdx) + (size_t)b * aStride + (size_t)row0 * K;
    base[2] = bufH(bIdx) + (size_t)b * bStride + (size_t)col0 * K;
    base[3] = bufL(bIdx) + (size_t)b * bStride + (size_t)col0 * K;

    uint32_t sb = smem_u32(dsm);
    wmma::fragment<wmma::accumulator, 16, 16, 16, float> acc[4][2];
#pragma unroll
    for (int mi = 0; mi < 4; mi++)
#pragma unroll
        for (int nj = 0; nj < 2; nj++) wmma::fill_fragment(acc[mi][nj], 0.0f);

    const int KT = K / KC;
    int lrow = tid >> 1;           // 0..127
    int lcc0 = (tid & 1) << 1;     // chunk index {0,2}

#define ISSUE(kt, st) do {                                                     \
        int _k0 = (kt) * KC;                                                   \
        uint32_t _s0 = sb + (st) * STAGEB;                                     \
        _Pragma("unroll")                                                      \
        for (int m = 0; m < 4; m++) {                                          \
            const bf16* _g = base[m] + (size_t)lrow * K + _k0;                 \
            uint32_t _sm = _s0 + m * TILEB + lrow * PADB;                      \
            CP_ASYNC(_sm + lcc0 * 16, _g + lcc0 * 8);                          \
            CP_ASYNC(_sm + (lcc0 + 1) * 16, _g + (lcc0 + 1) * 8);              \
        }                                                                      \
        CP_COMMIT();                                                           \
    } while (0)

    ISSUE(0, 0);
    ISSUE(1, 1);

    for (int kt = 0; kt < KT; kt++) {
        int st = kt % NSTAGE;
        // wait for k-tile kt (only kt and kt+1 can be in flight here)
        CP_WAIT(1);
        __syncthreads();  // (a) everyone done computing kt-1; (b) kt's data visible
        if (kt + 2 < KT) ISSUE(kt + 2, (kt + 2) % NSTAGE);

        const bf16* sAh = (const bf16*)(dsm + st * STAGEB + 0 * TILEB);
        const bf16* sAl = (const bf16*)(dsm + st * STAGEB + 1 * TILEB);
        const bf16* sBh = (const bf16*)(dsm + st * STAGEB + 2 * TILEB);
        const bf16* sBl = (const bf16*)(dsm + st * STAGEB + 3 * TILEB);

#pragma unroll
        for (int ks = 0; ks < KC; ks += 16) {
            // Load ALL fragments first, then 3 passes of 8 independent MMAs
            // (same-acc reuse distance 8 -> no RAW chains on accumulators).
            wmma::fragment<wmma::matrix_a, 16, 16, 16, bf16, wmma::row_major> fah[4], fal[4];
            wmma::fragment<wmma::matrix_b, 16, 16, 16, bf16, wmma::col_major> fbh[2], fbl[2];
#pragma unroll
            for (int nj = 0; nj < 2; nj++) {
                int nrow = warp_n * 32 + nj * 16;
                wmma::load_matrix_sync(fbh[nj], sBh + nrow * LDT + ks, LDT);
                wmma::load_matrix_sync(fbl[nj], sBl + nrow * LDT + ks, LDT);
            }
#pragma unroll
            for (int mi = 0; mi < 4; mi++) {
                int arow = warp_m * 64 + mi * 16;
                wmma::load_matrix_sync(fah[mi], sAh + arow * LDT + ks, LDT);
                wmma::load_matrix_sync(fal[mi], sAl + arow * LDT + ks, LDT);
            }
#pragma unroll
            for (int mi = 0; mi < 4; mi++)
#pragma unroll
                for (int nj = 0; nj < 2; nj++)
                    wmma::mma_sync(acc[mi][nj], fah[mi], fbh[nj], acc[mi][nj]);
#pragma unroll
            for (int mi = 0; mi < 4; mi++)
#pragma unroll
                for (int nj = 0; nj < 2; nj++)
                    wmma::mma_sync(acc[mi][nj], fah[mi], fbl[nj], acc[mi][nj]);
#pragma unroll
            for (int mi = 0; mi < 4; mi++)
#pragma unroll
                for (int nj = 0; nj < 2; nj++)
                    wmma::mma_sync(acc[mi][nj], fal[mi], fbh[nj], acc[mi][nj]);
        }
    }
    __syncthreads();  // all compute done before staging reuse

    // ---- epilogue: stage each 16x16 acc tile through smem ----
    float* stag = reinterpret_cast<float*>(dsm) + wid * 256;  // 1KB per warp
    int prow = lane >> 1, pc0 = (lane & 1) << 3;
#pragma unroll
    for (int mi = 0; mi < 4; mi++)
#pragma unroll
        for (int nj = 0; nj < 2; nj++) {
            wmma::store_matrix_sync(stag, acc[mi][nj], 16, wmma::mem_row_major);
            __syncwarp();
            int rr = row0 + warp_m * 64 + mi * 16 + prow;
            int cc0 = col0 + warp_n * 32 + nj * 16 + pc0;
#pragma unroll
            for (int p = 0; p < 8; p += 2)
                epi_pair(mode, b, rr, cc0 + p,
                         stag[prow * 16 + pc0 + p], stag[prow * 16 + pc0 + p + 1],
                         outH, Csrc, bias);
            __syncwarp();
        }
}

// ======================= launch =============================================
extern "C" void kernel_launch(void* const* d_in, const int* in_sizes, int n_in,
                              void* d_out, int out_size) {
    const float* C     = (const float*)d_in[0];
    const float* Q     = (const float*)d_in[1];
    const float* cmask = (const float*)d_in[2];
    const float* qmask = (const float*)d_in[3];
    const float* w     = (const float*)d_in[4];
    const float* out_w = (const float*)d_in[5];
    const float* out_b = (const float*)d_in[6];
    float* out         = (float*)d_out;

    static int smem_set = 0;
    if (!smem_set) {
        cudaFuncSetAttribute(wmma_gemm, cudaFuncAttributeMaxDynamicSharedMemorySize,
                             SMEM_GEMM);
        smem_set = 1;
    }

    // row dots
    rowdot_kernel<<<(BB * LC) / 8, 256>>>(C, w, 0, BB * LC);
    rowdot_kernel<<<(BB * LQ) / 8, 256>>>(Q, w + DD, 1, BB * LQ);

    // operand prep (bf16 splits + transposes)
    {
        size_t n = (size_t)BB * LC * DD;           // 8388608
        split_c_kernel<<<(unsigned)(n / 1024), 256>>>(C, w + 2 * DD);
    }
    {
        size_t n = (size_t)BB * LQ * DD;
        split4_kernel<<<(unsigned)(n / 1024), 256>>>(Q, 1 /*Q*/, n);
    }
    {
        size_t n = (size_t)DD * 4 * DD;
        split4_kernel<<<(unsigned)(n / 1024), 256>>>(out_w, 7 /*W*/, n);
    }
    transpose_split_kernel<<<dim3(DD / 32, LQ / 32, BB), dim3(32, 8)>>>(Q, 0, 2 /*QT*/, LQ, DD);
    transpose_split_kernel<<<dim3(DD / 32, LC / 32, BB), dim3(32, 8)>>>(C, 0, 3 /*CT*/, LC, DD);

    // S = (C*w3) @ Q^T + c1 + q2
    wmma_gemm<<<dim3(LQ / 128, LC / 128, BB), 256, SMEM_GEMM>>>(
        0 /*CW*/, 1 /*Q*/, (size_t)LC * DD, (size_t)LQ * DD, DD, 0, nullptr, nullptr, nullptr);

    // softmaxes
    softmax_row_kernel<<<dim3(LC, BB), 256>>>(qmask);        // -> S1 bf16 hi/lo
    softmax_col_kernel<<<dim3(LQ / 256, BB), 256>>>(cmask);  // -> g_S2 fp32
    transpose_split_kernel<<<dim3(LQ / 32, LC / 32, BB), dim3(32, 8)>>>(nullptr, 1 /*g_S2*/, 5 /*S2T*/, LC, LQ);

    // T = S2^T @ C   (A = S2T [LQ x LC], B = CT [DD x LC])
    wmma_gemm<<<dim3(DD / 128, LQ / 128, BB), 256, SMEM_GEMM>>>(
        5 /*S2T*/, 3 /*CT*/, (size_t)LQ * LC, (size_t)DD * LC, LC, 1, nullptr, nullptr, nullptr);
    transpose_split_kernel<<<dim3(DD / 32, LQ / 32, BB), dim3(32, 8)>>>(nullptr, 2 /*g_T*/, 6 /*TT*/, LQ, DD);

    // A = S1 @ Q  -> X[:,512:1024] and C*A -> X[:,1024:1536]
    wmma_gemm<<<dim3(DD / 128, LC / 128, BB), 256, SMEM_GEMM>>>(
        4 /*S1*/, 2 /*QT*/, (size_t)LC * LQ, (size_t)DD * LQ, LQ, 2, nullptr, C, nullptr);

    // Bm = S1 @ T -> C*Bm -> X[:,1536:2048]
    wmma_gemm<<<dim3(DD / 128, LC / 128, BB), 256, SMEM_GEMM>>>(
        4 /*S1*/, 6 /*TT*/, (size_t)LC * LQ, (size_t)DD * LQ, LQ, 3, nullptr, C, nullptr);

    // out = X @ out_w^T + out_b   (M = BB*LC, N = DD, K = 4*DD)
    wmma_gemm<<<dim3(DD / 128, (BB * LC) / 128, 1), 256, SMEM_GEMM>>>(
        8 /*X*/, 7 /*W*/, 0, 0, 4 * DD, 4, out, nullptr, out_b);
}

// round 14
// speedup vs baseline: 1.5144x; 1.0827x over previous
#include <cuda_runtime.h>
#include <cuda_bf16.h>
#include <mma.h>
#include <stdint.h>
#include <math.h>

using namespace nvcuda;

#define BB 16
#define LC 1024
#define LQ 512
#define DD 512
#define NEG_INF_F (-1e30f)

typedef __nv_bfloat16 bf16;

// ======================= scratch (static device arrays) =====================
__device__ float g_c1[BB * LC];
__device__ float g_q2[BB * LQ];
__device__ float g_S [(size_t)BB * LC * LQ];   // logits
__device__ float g_S2[(size_t)BB * LC * LQ];   // col softmax fp32
__device__ float g_T [(size_t)BB * LQ * DD];   // S2^T C fp32

__device__ bf16 g_CWh[(size_t)BB * LC * DD], g_CWl[(size_t)BB * LC * DD];
__device__ bf16 g_Qh [(size_t)BB * LQ * DD], g_Ql [(size_t)BB * LQ * DD];
__device__ bf16 g_QTh[(size_t)BB * DD * LQ], g_QTl[(size_t)BB * DD * LQ];
__device__ bf16 g_CTh[(size_t)BB * DD * LC], g_CTl[(size_t)BB * DD * LC];
__device__ bf16 g_S1h[(size_t)BB * LC * LQ], g_S1l[(size_t)BB * LC * LQ];
__device__ bf16 g_S2Th[(size_t)BB * LQ * LC], g_S2Tl[(size_t)BB * LQ * LC];
__device__ bf16 g_TTh[(size_t)BB * DD * LQ], g_TTl[(size_t)BB * DD * LQ];
__device__ bf16 g_Wh [(size_t)DD * 4 * DD],  g_Wl [(size_t)DD * 4 * DD];
__device__ bf16 g_Xh [(size_t)BB * LC * 4 * DD], g_Xl[(size_t)BB * LC * 4 * DD];

// Device-side buffer resolution — NEVER pass __device__ symbols from host.
// ids: 0=CW 1=Q 2=QT 3=CT 4=S1 5=S2T 6=TT 7=W 8=X
__device__ __forceinline__ bf16* bufH(int i) {
    switch (i) {
        case 0: return g_CWh; case 1: return g_Qh;  case 2: return g_QTh;
        case 3: return g_CTh; case 4: return g_S1h; case 5: return g_S2Th;
        case 6: return g_TTh; case 7: return g_Wh;  default: return g_Xh;
    }
}
__device__ __forceinline__ bf16* bufL(int i) {
    switch (i) {
        case 0: return g_CWl; case 1: return g_Ql;  case 2: return g_QTl;
        case 3: return g_CTl; case 4: return g_S1l; case 5: return g_S2Tl;
        case 6: return g_TTl; case 7: return g_Wl;  default: return g_Xl;
    }
}

// ======================= helpers ============================================
__device__ __forceinline__ void bsplit(float x, bf16& h, bf16& l) {
    h = __float2bfloat16(x);
    l = __float2bfloat16(x - __bfloat162float(h));
}
#define CP_ASYNC(sa, ga) asm volatile( \
    "cp.async.cg.shared.global [%0], [%1], 16;" :: "r"(sa), "l"(ga))
#define CP_COMMIT() asm volatile("cp.async.commit_group;" ::: "memory")
#define CP_WAIT(n) asm volatile("cp.async.wait_group %0;" :: "n"(n) : "memory")
__device__ __forceinline__ uint32_t smem_u32(const void* p) {
    uint32_t a;
    asm("{ .reg .u64 t; cvta.to.shared.u64 t, %1; cvt.u32.u64 %0, t; }"
        : "=r"(a) : "l"(p));
    return a;
}

// ======================= small kernels ======================================
__global__ void rowdot_kernel(const float* __restrict__ X, const float* __restrict__ w,
                              int which, int nrows) {
    float* out = which ? g_q2 : g_c1;
    int gw = (blockIdx.x * blockDim.x + threadIdx.x) >> 5;
    int lane = threadIdx.x & 31;
    if (gw >= nrows) return;
    const float* row = X + (size_t)gw * DD;
    float s = 0.f;
#pragma unroll 4
    for (int k = lane; k < DD; k += 32) s = fmaf(row[k], w[k], s);
#pragma unroll
    for (int o = 16; o; o >>= 1) s += __shfl_xor_sync(0xffffffffu, s, o);
    if (lane == 0) out[gw] = s;
}

__device__ __forceinline__ void split2_store(bf16* h, bf16* l, size_t idx,
                                             float a, float b) {
    bf16 h0, l0, h1, l1;
    bsplit(a, h0, l0);
    bsplit(b, h1, l1);
    *(__nv_bfloat162*)(h + idx) = __halves2bfloat162(h0, h1);
    *(__nv_bfloat162*)(l + idx) = __halves2bfloat162(l0, l1);
}

// C: one read -> CW (scaled) split AND X[:,0:512] split
__global__ void split_c_kernel(const float* __restrict__ C, const float* __restrict__ w3) {
    size_t i = ((size_t)blockIdx.x * blockDim.x + threadIdx.x) * 4;  // < BB*LC*DD
    size_t row = i >> 9;
    int c = (int)(i & (DD - 1));
    float4 v = *(const float4*)(C + i);
    float4 s = *(const float4*)(w3 + c);
    split2_store(g_Xh, g_Xl, row * (4 * DD) + c, v.x, v.y);
    split2_store(g_Xh, g_Xl, row * (4 * DD) + c + 2, v.z, v.w);
    split2_store(g_CWh, g_CWl, i, v.x * s.x, v.y * s.y);
    split2_store(g_CWh, g_CWl, i + 2, v.z * s.z, v.w * s.w);
}

__global__ void split4_kernel(const float* __restrict__ src, int dstIdx, size_t n) {
    size_t i = ((size_t)blockIdx.x * blockDim.x + threadIdx.x) * 4;
    if (i >= n) return;
    float4 v = *(const float4*)(src + i);
    bf16* h = bufH(dstIdx);
    bf16* l = bufL(dstIdx);
    split2_store(h, l, i, v.x, v.y);
    split2_store(h, l, i + 2, v.z, v.w);
}

// src fp32 [R x Cc] per batch -> dst bf16 hi/lo [Cc x R]
// srcSel: 0 = srcParam (harness ptr), 1 = g_S2, 2 = g_T
__global__ void transpose_split_kernel(const float* __restrict__ srcParam, int srcSel,
                                       int dstIdx, int R, int Cc) {
    __shared__ float t[32][33];
    const float* src = (srcSel == 0) ? srcParam : (srcSel == 1 ? g_S2 : g_T);
    bf16* h = bufH(dstIdx);
    bf16* l = bufL(dstIdx);
    int b = blockIdx.z;
    const float* S = src + (size_t)b * R * Cc;
    size_t ob = (size_t)b * R * Cc;
    int c0 = blockIdx.x * 32, r0 = blockIdx.y * 32;
    int tx = threadIdx.x, ty = threadIdx.y;
#pragma unroll
    for (int j = 0; j < 32; j += 8)
        t[ty + j][tx] = S[(size_t)(r0 + ty + j) * Cc + c0 + tx];
    __syncthreads();
#pragma unroll
    for (int j = 0; j < 32; j += 8) {
        float v = t[tx][ty + j];
        size_t o = ob + (size_t)(c0 + ty + j) * R + r0 + tx;
        bf16 hh, ll;
        bsplit(v, hh, ll);
        h[o] = hh;
        l[o] = ll;
    }
}

__global__ void softmax_row_kernel(const float* __restrict__ qmask) {
    __shared__ float sred[64];
    int i = blockIdx.x, b = blockIdx.y;
    int t = threadIdx.x;
    size_t base = ((size_t)b * LC + i) * LQ;
    const float* srow = g_S + base;
    float m0 = qmask[b * LQ + t], m1 = qmask[b * LQ + t + 256];
    float x0 = srow[t] * m0 + (1.f - m0) * NEG_INF_F;
    float x1 = srow[t + 256] * m1 + (1.f - m1) * NEG_INF_F;
    float v = fmaxf(x0, x1);
    int lane = t & 31, wid = t >> 5;
#pragma unroll
    for (int o = 16; o; o >>= 1) v = fmaxf(v, __shfl_xor_sync(0xffffffffu, v, o));
    if (lane == 0) sred[wid] = v;
    __syncthreads();
    if (t < 32) {
        float w2 = (t < 8) ? sred[t] : -3e38f;
#pragma unroll
        for (int o = 4; o; o >>= 1) w2 = fmaxf(w2, __shfl_xor_sync(0xffffffffu, w2, o));
        if (t == 0) sred[32] = w2;
    }
    __syncthreads();
    float mx = sred[32];
    float e0 = __expf(x0 - mx), e1 = __expf(x1 - mx);
    v = e0 + e1;
#pragma unroll
    for (int o = 16; o; o >>= 1) v += __shfl_xor_sync(0xffffffffu, v, o);
    if (lane == 0) sred[wid] = v;
    __syncthreads();
    if (t < 32) {
        float w2 = (t < 8) ? sred[t] : 0.f;
#pragma unroll
        for (int o = 4; o; o >>= 1) w2 += __shfl_xor_sync(0xffffffffu, w2, o);
        if (t == 0) sred[33] = w2;
    }
    __syncthreads();
    float inv = 1.f / sred[33];
    bsplit(e0 * inv, g_S1h[base + t], g_S1l[base + t]);
    bsplit(e1 * inv, g_S1h[base + t + 256], g_S1l[base + t + 256]);
}

__global__ void softmax_col_kernel(const float* __restrict__ cmask) {
    int j = blockIdx.x * blockDim.x + threadIdx.x;
    int b = blockIdx.y;
    const float* Sb = g_S + (size_t)b * LC * LQ;
    float* Ob = g_S2 + (size_t)b * LC * LQ;
    const float* cm = cmask + b * LC;
    float m = -3e38f, l = 0.f;
    for (int i = 0; i < LC; i++) {
        float cmi = cm[i];
        float x = Sb[(size_t)i * LQ + j] * cmi + (1.f - cmi) * NEG_INF_F;
        float nm = fmaxf(m, x);
        l = l * __expf(m - nm) + __expf(x - nm);
        m = nm;
    }
    float inv = 1.f / l;
    for (int i = 0; i < LC; i++) {
        float cmi = cm[i];
        float x = Sb[(size_t)i * LQ + j] * cmi + (1.f - cmi) * NEG_INF_F;
        Ob[(size_t)i * LQ + j] = __expf(x - m) * inv;
    }
}

// ======================= WMMA GEMM (128x128, 2-stage, 2 CTAs/SM) ============
// D[128x128] per CTA; A,B bf16 hi/lo K-major [rows x K] row-major.
// bf16x3: D = Ah*Bh + Ah*Bl + Al*Bh, fp32 accumulate (wmma).
#define KC 32
#define LDT 40                         // padded smem row stride (80 B)
#define PADB 80
#define TILEB (128 * PADB)             // 10240 B per matrix tile
#define STAGEB (4 * TILEB)             // Ah, Al, Bh, Bl = 40960 B
#define SMEM_GEMM (2 * STAGEB)         // 81920 B double-buffered

__device__ __forceinline__ void epi_pair(int mode, int b, int row, int col,
                                         float v0, float v1, float* outF,
                                         const float* Csrc, const float* bias) {
    if (mode == 0) {  // S logits += c1[row] + q2[col]
        size_t grow = (size_t)b * LC + row;
        float c1v = g_c1[b * LC + row];
        float2 o = make_float2(v0 + c1v + g_q2[b * LQ + col],
                               v1 + c1v + g_q2[b * LQ + col + 1]);
        *(float2*)(g_S + grow * LQ + col) = o;
    } else if (mode == 1) {  // plain fp32 (T)
        *(float2*)(g_T + ((size_t)b * LQ + row) * DD + col) = make_float2(v0, v1);
    } else if (mode == 2 || mode == 3) {  // X features
        size_t grow = (size_t)b * LC + row;
        const float* crow = Csrc + grow * DD + col;
        size_t xrow = grow * (size_t)(4 * DD);
        bf16 h0, l0, h1, l1;
        if (mode == 2) {
            bsplit(v0, h0, l0);
            bsplit(v1, h1, l1);
            *(__nv_bfloat162*)(g_Xh + xrow + DD + col) = __halves2bfloat162(h0, h1);
            *(__nv_bfloat162*)(g_Xl + xrow + DD + col) = __halves2bfloat162(l0, l1);
        }
        int off = (mode == 2) ? 2 * DD : 3 * DD;
        bsplit(crow[0] * v0, h0, l0);
        bsplit(crow[1] * v1, h1, l1);
        *(__nv_bfloat162*)(g_Xh + xrow + off + col) = __halves2bfloat162(h0, h1);
        *(__nv_bfloat162*)(g_Xl + xrow + off + col) = __halves2bfloat162(l0, l1);
    } else {  // mode 4: final + bias (row is global over BB*LC; outF = harness out)
        *(float2*)(outF + (size_t)row * DD + col) =
            make_float2(v0 + bias[col], v1 + bias[col + 1]);
    }
}

__global__ void __launch_bounds__(256, 2)
wmma_gemm(int aIdx, int bIdx, size_t aStride, size_t bStride, int K, int mode,
          float* __restrict__ outH,
          const float* __restrict__ Csrc, const float* __restrict__ bias) {
    extern __shared__ __align__(16) char dsm[];
    int tid = threadIdx.x, lane = tid & 31, wid = tid >> 5;
    int warp_m = wid & 1, warp_n = wid >> 1;  // 2 x 4 warps; warp tile 64 x 32
    int b = blockIdx.z;
    int row0 = blockIdx.y << 7, col0 = blockIdx.x << 7;

    const bf16* base[4];
    base[0] = bufH(aIdx) + (size_t)b * aStride + (size_t)row0 * K;
    base[1] = bufL(aIdx) + (size_t)b * aStride + (size_t)row0 * K;
    base[2] = bufH(bIdx) + (size_t)b * bStride + (size_t)col0 * K;
    base[3] = bufL(bIdx) + (size_t)b * bStride + (size_t)col0 * K;

    uint32_t sb = smem_u32(dsm);
    wmma::fragment<wmma::accumulator, 16, 16, 16, float> acc[4][2];
#pragma unroll
    for (int mi = 0; mi < 4; mi++)
#pragma unroll
        for (int nj = 0; nj < 2; nj++) wmma::fill_fragment(acc[mi][nj], 0.0f);

    const int KT = K / KC;
    int lrow = tid >> 1;           // 0..127
    int lcc0 = (tid & 1) << 1;     // chunk index {0,2}

#define ISSUE(kt, st) do {                                                     \
        int _k0 = (kt) * KC;                                                   \
        uint32_t _s0 = sb + (st) * STAGEB;                                     \
        _Pragma("unroll")                                                      \
        for (int m = 0; m < 4; m++) {                                          \
            const bf16* _g = base[m] + (size_t)lrow * K + _k0;                 \
            uint32_t _sm = _s0 + m * TILEB + lrow * PADB;                      \
            CP_ASYNC(_sm + lcc0 * 16, _g + lcc0 * 8);                          \
            CP_ASYNC(_sm + (lcc0 + 1) * 16, _g + (lcc0 + 1) * 8);              \
        }                                                                      \
        CP_COMMIT();                                                           \
    } while (0)

    ISSUE(0, 0);

    for (int kt = 0; kt < KT; kt++) {
        int st = kt & 1;
        if (kt + 1 < KT) {
            ISSUE(kt + 1, st ^ 1);
            CP_WAIT(1);
        } else {
            CP_WAIT(0);
        }
        __syncthreads();  // cp.async data visible to all warps

        const bf16* sAh = (const bf16*)(dsm + st * STAGEB + 0 * TILEB);
        const bf16* sAl = (const bf16*)(dsm + st * STAGEB + 1 * TILEB);
        const bf16* sBh = (const bf16*)(dsm + st * STAGEB + 2 * TILEB);
        const bf16* sBl = (const bf16*)(dsm + st * STAGEB + 3 * TILEB);

#pragma unroll
        for (int ks = 0; ks < KC; ks += 16) {
            wmma::fragment<wmma::matrix_b, 16, 16, 16, bf16, wmma::col_major> fbh[2], fbl[2];
#pragma unroll
            for (int nj = 0; nj < 2; nj++) {
                int nrow = warp_n * 32 + nj * 16;
                wmma::load_matrix_sync(fbh[nj], sBh + nrow * LDT + ks, LDT);
                wmma::load_matrix_sync(fbl[nj], sBl + nrow * LDT + ks, LDT);
            }
#pragma unroll
            for (int mi = 0; mi < 4; mi++) {
                int arow = warp_m * 64 + mi * 16;
                wmma::fragment<wmma::matrix_a, 16, 16, 16, bf16, wmma::row_major> fah, fal;
                wmma::load_matrix_sync(fah, sAh + arow * LDT + ks, LDT);
                wmma::load_matrix_sync(fal, sAl + arow * LDT + ks, LDT);
#pragma unroll
                for (int nj = 0; nj < 2; nj++) {
                    wmma::mma_sync(acc[mi][nj], fah, fbh[nj], acc[mi][nj]);
                    wmma::mma_sync(acc[mi][nj], fah, fbl[nj], acc[mi][nj]);
                    wmma::mma_sync(acc[mi][nj], fal, fbh[nj], acc[mi][nj]);
                }
            }
        }
        __syncthreads();  // compute done before next ISSUE overwrites this stage
    }

    // ---- epilogue: stage each 16x16 acc tile through smem ----
    float* stag = reinterpret_cast<float*>(dsm) + wid * 256;  // 1KB per warp
    int prow = lane >> 1, pc0 = (lane & 1) << 3;
#pragma unroll
    for (int mi = 0; mi < 4; mi++)
#pragma unroll
        for (int nj = 0; nj < 2; nj++) {
            wmma::store_matrix_sync(stag, acc[mi][nj], 16, wmma::mem_row_major);
            __syncwarp();
            int rr = row0 + warp_m * 64 + mi * 16 + prow;
            int cc0 = col0 + warp_n * 32 + nj * 16 + pc0;
#pragma unroll
            for (int p = 0; p < 8; p += 2)
                epi_pair(mode, b, rr, cc0 + p,
                         stag[prow * 16 + pc0 + p], stag[prow * 16 + pc0 + p + 1],
                         outH, Csrc, bias);
            __syncwarp();
        }
}

// ======================= launch =============================================
extern "C" void kernel_launch(void* const* d_in, const int* in_sizes, int n_in,
                              void* d_out, int out_size) {
    const float* C     = (const float*)d_in[0];
    const float* Q     = (const float*)d_in[1];
    const float* cmask = (const float*)d_in[2];
    const float* qmask = (const float*)d_in[3];
    const float* w     = (const float*)d_in[4];
    const float* out_w = (const float*)d_in[5];
    const float* out_b = (const float*)d_in[6];
    float* out         = (float*)d_out;

    static int smem_set = 0;
    if (!smem_set) {
        cudaFuncSetAttribute(wmma_gemm, cudaFuncAttributeMaxDynamicSharedMemorySize,
                             SMEM_GEMM);
        smem_set = 1;
    }

    // row dots
    rowdot_kernel<<<(BB * LC) / 8, 256>>>(C, w, 0, BB * LC);
    rowdot_kernel<<<(BB * LQ) / 8, 256>>>(Q, w + DD, 1, BB * LQ);

    // operand prep (bf16 splits + transposes)
    {
        size_t n = (size_t)BB * LC * DD;           // 8388608
        split_c_kernel<<<(unsigned)(n / 1024), 256>>>(C, w + 2 * DD);
    }
    {
        size_t n = (size_t)BB * LQ * DD;
        split4_kernel<<<(unsigned)(n / 1024), 256>>>(Q, 1 /*Q*/, n);
    }
    {
        size_t n = (size_t)DD * 4 * DD;
        split4_kernel<<<(unsigned)(n / 1024), 256>>>(out_w, 7 /*W*/, n);
    }
    transpose_split_kernel<<<dim3(DD / 32, LQ / 32, BB), dim3(32, 8)>>>(Q, 0, 2 /*QT*/, LQ, DD);
    transpose_split_kernel<<<dim3(DD / 32, LC / 32, BB), dim3(32, 8)>>>(C, 0, 3 /*CT*/, LC, DD);

    // S = (C*w3) @ Q^T + c1 + q2
    wmma_gemm<<<dim3(LQ / 128, LC / 128, BB), 256, SMEM_GEMM>>>(
        0 /*CW*/, 1 /*Q*/, (size_t)LC * DD, (size_t)LQ * DD, DD, 0, nullptr, nullptr, nullptr);

    // softmaxes
    softmax_row_kernel<<<dim3(LC, BB), 256>>>(qmask);        // -> S1 bf16 hi/lo
    softmax_col_kernel<<<dim3(LQ / 256, BB), 256>>>(cmask);  // -> g_S2 fp32
    transpose_split_kernel<<<dim3(LQ / 32, LC / 32, BB), dim3(32, 8)>>>(nullptr, 1 /*g_S2*/, 5 /*S2T*/, LC, LQ);

    // T = S2^T @ C   (A = S2T [LQ x LC], B = CT [DD x LC])
    wmma_gemm<<<dim3(DD / 128, LQ / 128, BB), 256, SMEM_GEMM>>>(
        5 /*S2T*/, 3 /*CT*/, (size_t)LQ * LC, (size_t)DD * LC, LC, 1, nullptr, nullptr, nullptr);
    transpose_split_kernel<<<dim3(DD / 32, LQ / 32, BB), dim3(32, 8)>>>(nullptr, 2 /*g_T*/, 6 /*TT*/, LQ, DD);

    // A = S1 @ Q  -> X[:,512:1024] and C*A -> X[:,1024:1536]
    wmma_gemm<<<dim3(DD / 128, LC / 128, BB), 256, SMEM_GEMM>>>(
        4 /*S1*/, 2 /*QT*/, (size_t)LC * LQ, (size_t)DD * LQ, LQ, 2, nullptr, C, nullptr);

    // Bm = S1 @ T -> C*Bm -> X[:,1536:2048]
    wmma_gemm<<<dim3(DD / 128, LC / 128, BB), 256, SMEM_GEMM>>>(
        4 /*S1*/, 6 /*TT*/, (size_t)LC * LQ, (size_t)DD * LQ, LQ, 3, nullptr, C, nullptr);

    // out = X @ out_w^T + out_b   (M = BB*LC, N = DD, K = 4*DD)
    wmma_gemm<<<dim3(DD / 128, (BB * LC) / 128, 1), 256, SMEM_GEMM>>>(
        8 /*X*/, 7 /*W*/, 0, 0, 4 * DD, 4, out, nullptr, out_b);
}

// round 15
// speedup vs baseline: 1.9465x; 1.2854x over previous
#include <cuda_runtime.h>
#include <cuda_bf16.h>
#include <cuda_fp16.h>
#include <mma.h>
#include <stdint.h>
#include <math.h>

using namespace nvcuda;

#define BB 16
#define LC 1024
#define LQ 512
#define DD 512
#define NEG_INF_F (-1e30f)

typedef __nv_bfloat16 bf16;

// ======================= scratch (static device arrays) =====================
__device__ float g_c1[BB * LC];
__device__ float g_q2[BB * LQ];
__device__ float g_S [(size_t)BB * LC * LQ];   // logits
__device__ float g_S2[(size_t)BB * LC * LQ];   // col softmax fp32
__device__ float g_T [(size_t)BB * LQ * DD];   // S2^T C fp32

// bf16 pairs (S-GEMM operands only)
__device__ bf16 g_CWh[(size_t)BB * LC * DD], g_CWl[(size_t)BB * LC * DD];
__device__ bf16 g_Qh [(size_t)BB * LQ * DD], g_Ql [(size_t)BB * LQ * DD];

// fp16: A-side pairs
__device__ half g_hS1h[(size_t)BB * LC * LQ], g_hS1l[(size_t)BB * LC * LQ];
__device__ half g_hS2Th[(size_t)BB * LQ * LC], g_hS2Tl[(size_t)BB * LQ * LC];
__device__ half g_hXh[(size_t)BB * LC * 4 * DD], g_hXl[(size_t)BB * LC * 4 * DD];
// fp16: B-side singles
__device__ half g_hQT[(size_t)BB * DD * LQ];
__device__ half g_hCT[(size_t)BB * DD * LC];
__device__ half g_hTT[(size_t)BB * DD * LQ];
__device__ half g_hW [(size_t)DD * 4 * DD];

// Device-side buffer resolution — NEVER pass __device__ symbols from host.
__device__ __forceinline__ bf16* bufH(int i) { return i ? g_Qh : g_CWh; }
__device__ __forceinline__ bf16* bufL(int i) { return i ? g_Ql : g_CWl; }
// fp16 A pairs: 0=S1 1=S2T 2=X
__device__ __forceinline__ half* habufH(int i) {
    switch (i) { case 0: return g_hS1h; case 1: return g_hS2Th; default: return g_hXh; }
}
__device__ __forceinline__ half* habufL(int i) {
    switch (i) { case 0: return g_hS1l; case 1: return g_hS2Tl; default: return g_hXl; }
}
// fp16 B singles: 0=QT 1=CT 2=TT 3=W
__device__ __forceinline__ half* hbbuf(int i) {
    switch (i) { case 0: return g_hQT; case 1: return g_hCT;
                 case 2: return g_hTT; default: return g_hW; }
}

// ======================= helpers ============================================
__device__ __forceinline__ void bsplit(float x, bf16& h, bf16& l) {
    h = __float2bfloat16(x);
    l = __float2bfloat16(x - __bfloat162float(h));
}
__device__ __forceinline__ void hsplit(float x, half& h, half& l) {
    h = __float2half(x);
    l = __float2half(x - __half2float(h));
}
#define CP_ASYNC(sa, ga) asm volatile( \
    "cp.async.cg.shared.global [%0], [%1], 16;" :: "r"(sa), "l"(ga))
#define CP_COMMIT() asm volatile("cp.async.commit_group;" ::: "memory")
#define CP_WAIT(n) asm volatile("cp.async.wait_group %0;" :: "n"(n) : "memory")
__device__ __forceinline__ uint32_t smem_u32(const void* p) {
    uint32_t a;
    asm("{ .reg .u64 t; cvta.to.shared.u64 t, %1; cvt.u32.u64 %0, t; }"
        : "=r"(a) : "l"(p));
    return a;
}

// ======================= small kernels ======================================
__global__ void rowdot_kernel(const float* __restrict__ X, const float* __restrict__ w,
                              int which, int nrows) {
    float* out = which ? g_q2 : g_c1;
    int gw = (blockIdx.x * blockDim.x + threadIdx.x) >> 5;
    int lane = threadIdx.x & 31;
    if (gw >= nrows) return;
    const float* row = X + (size_t)gw * DD;
    float s = 0.f;
#pragma unroll 4
    for (int k = lane; k < DD; k += 32) s = fmaf(row[k], w[k], s);
#pragma unroll
    for (int o = 16; o; o >>= 1) s += __shfl_xor_sync(0xffffffffu, s, o);
    if (lane == 0) out[gw] = s;
}

__device__ __forceinline__ void bsplit2_store(bf16* h, bf16* l, size_t idx,
                                              float a, float b) {
    bf16 h0, l0, h1, l1;
    bsplit(a, h0, l0);
    bsplit(b, h1, l1);
    *(__nv_bfloat162*)(h + idx) = __halves2bfloat162(h0, h1);
    *(__nv_bfloat162*)(l + idx) = __halves2bfloat162(l0, l1);
}
__device__ __forceinline__ void hsplit2_store(half* h, half* l, size_t idx,
                                              float a, float b) {
    half h0, l0, h1, l1;
    hsplit(a, h0, l0);
    hsplit(b, h1, l1);
    *(__half2*)(h + idx) = __halves2half2(h0, h1);
    *(__half2*)(l + idx) = __halves2half2(l0, l1);
}

// C: one read -> CW bf16 pair (scaled) AND X[:,0:512] fp16 pair
__global__ void split_c_kernel(const float* __restrict__ C, const float* __restrict__ w3) {
    size_t i = ((size_t)blockIdx.x * blockDim.x + threadIdx.x) * 4;  // < BB*LC*DD
    size_t row = i >> 9;
    int c = (int)(i & (DD - 1));
    float4 v = *(const float4*)(C + i);
    float4 s = *(const float4*)(w3 + c);
    hsplit2_store(g_hXh, g_hXl, row * (4 * DD) + c, v.x, v.y);
    hsplit2_store(g_hXh, g_hXl, row * (4 * DD) + c + 2, v.z, v.w);
    bsplit2_store(g_CWh, g_CWl, i, v.x * s.x, v.y * s.y);
    bsplit2_store(g_CWh, g_CWl, i + 2, v.z * s.z, v.w * s.w);
}

// fp32 -> bf16 pair (Q for S-GEMM)
__global__ void split4_bf16_kernel(const float* __restrict__ src, int dstIdx, size_t n) {
    size_t i = ((size_t)blockIdx.x * blockDim.x + threadIdx.x) * 4;
    if (i >= n) return;
    float4 v = *(const float4*)(src + i);
    bf16* h = bufH(dstIdx);
    bf16* l = bufL(dstIdx);
    bsplit2_store(h, l, i, v.x, v.y);
    bsplit2_store(h, l, i + 2, v.z, v.w);
}

// fp32 -> single fp16 (W)
__global__ void split4_h_kernel(const float* __restrict__ src, int dstIdx, size_t n) {
    size_t i = ((size_t)blockIdx.x * blockDim.x + threadIdx.x) * 4;
    if (i >= n) return;
    float4 v = *(const float4*)(src + i);
    half* d = hbbuf(dstIdx);
    *(__half2*)(d + i) = __halves2half2(__float2half(v.x), __float2half(v.y));
    *(__half2*)(d + i + 2) = __halves2half2(__float2half(v.z), __float2half(v.w));
}

// src fp32 [R x Cc] per batch -> fp16 transposed [Cc x R].
// srcSel: 0 = srcParam, 1 = g_S2, 2 = g_T. pairMode: 0 = single (B table), 1 = pair (A table)
__global__ void transpose_h_kernel(const float* __restrict__ srcParam, int srcSel,
                                   int dstIdx, int pairMode, int R, int Cc) {
    __shared__ float t[32][33];
    const float* src = (srcSel == 0) ? srcParam : (srcSel == 1 ? g_S2 : g_T);
    int b = blockIdx.z;
    const float* S = src + (size_t)b * R * Cc;
    size_t ob = (size_t)b * R * Cc;
    int c0 = blockIdx.x * 32, r0 = blockIdx.y * 32;
    int tx = threadIdx.x, ty = threadIdx.y;
#pragma unroll
    for (int j = 0; j < 32; j += 8)
        t[ty + j][tx] = S[(size_t)(r0 + ty + j) * Cc + c0 + tx];
    __syncthreads();
    if (pairMode) {
        half* h = habufH(dstIdx);
        half* l = habufL(dstIdx);
#pragma unroll
        for (int j = 0; j < 32; j += 8) {
            float v = t[tx][ty + j];
            size_t o = ob + (size_t)(c0 + ty + j) * R + r0 + tx;
            half hh, ll;
            hsplit(v, hh, ll);
            h[o] = hh;
            l[o] = ll;
        }
    } else {
        half* d = hbbuf(dstIdx);
#pragma unroll
        for (int j = 0; j < 32; j += 8) {
            float v = t[tx][ty + j];
            size_t o = ob + (size_t)(c0 + ty + j) * R + r0 + tx;
            d[o] = __float2half(v);
        }
    }
}

__global__ void softmax_row_kernel(const float* __restrict__ qmask) {
    __shared__ float sred[64];
    int i = blockIdx.x, b = blockIdx.y;
    int t = threadIdx.x;
    size_t base = ((size_t)b * LC + i) * LQ;
    const float* srow = g_S + base;
    float m0 = qmask[b * LQ + t], m1 = qmask[b * LQ + t + 256];
    float x0 = srow[t] * m0 + (1.f - m0) * NEG_INF_F;
    float x1 = srow[t + 256] * m1 + (1.f - m1) * NEG_INF_F;
    float v = fmaxf(x0, x1);
    int lane = t & 31, wid = t >> 5;
#pragma unroll
    for (int o = 16; o; o >>= 1) v = fmaxf(v, __shfl_xor_sync(0xffffffffu, v, o));
    if (lane == 0) sred[wid] = v;
    __syncthreads();
    if (t < 32) {
        float w2 = (t < 8) ? sred[t] : -3e38f;
#pragma unroll
        for (int o = 4; o; o >>= 1) w2 = fmaxf(w2, __shfl_xor_sync(0xffffffffu, w2, o));
        if (t == 0) sred[32] = w2;
    }
    __syncthreads();
    float mx = sred[32];
    float e0 = __expf(x0 - mx), e1 = __expf(x1 - mx);
    v = e0 + e1;
#pragma unroll
    for (int o = 16; o; o >>= 1) v += __shfl_xor_sync(0xffffffffu, v, o);
    if (lane == 0) sred[wid] = v;
    __syncthreads();
    if (t < 32) {
        float w2 = (t < 8) ? sred[t] : 0.f;
#pragma unroll
        for (int o = 4; o; o >>= 1) w2 += __shfl_xor_sync(0xffffffffu, w2, o);
        if (t == 0) sred[33] = w2;
    }
    __syncthreads();
    float inv = 1.f / sred[33];
    hsplit(e0 * inv, g_hS1h[base + t], g_hS1l[base + t]);
    hsplit(e1 * inv, g_hS1h[base + t + 256], g_hS1l[base + t + 256]);
}

__global__ void softmax_col_kernel(const float* __restrict__ cmask) {
    int j = blockIdx.x * blockDim.x + threadIdx.x;
    int b = blockIdx.y;
    const float* Sb = g_S + (size_t)b * LC * LQ;
    float* Ob = g_S2 + (size_t)b * LC * LQ;
    const float* cm = cmask + b * LC;
    float m = -3e38f, l = 0.f;
    for (int i = 0; i < LC; i++) {
        float cmi = cm[i];
        float x = Sb[(size_t)i * LQ + j] * cmi + (1.f - cmi) * NEG_INF_F;
        float nm = fmaxf(m, x);
        l = l * __expf(m - nm) + __expf(x - nm);
        m = nm;
    }
    float inv = 1.f / l;
    for (int i = 0; i < LC; i++) {
        float cmi = cm[i];
        float x = Sb[(size_t)i * LQ + j] * cmi + (1.f - cmi) * NEG_INF_F;
        Ob[(size_t)i * LQ + j] = __expf(x - m) * inv;
    }
}

// ======================= shared epilogue ====================================
__device__ __forceinline__ void epi_pair(int mode, int b, int row, int col,
                                         float v0, float v1, float* outF,
                                         const float* Csrc, const float* bias) {
    if (mode == 0) {  // S logits += c1[row] + q2[col]
        size_t grow = (size_t)b * LC + row;
        float c1v = g_c1[b * LC + row];
        float2 o = make_float2(v0 + c1v + g_q2[b * LQ + col],
                               v1 + c1v + g_q2[b * LQ + col + 1]);
        *(float2*)(g_S + grow * LQ + col) = o;
    } else if (mode == 1) {  // plain fp32 (T)
        *(float2*)(g_T + ((size_t)b * LQ + row) * DD + col) = make_float2(v0, v1);
    } else if (mode == 2 || mode == 3) {  // X features (fp16 pairs)
        size_t grow = (size_t)b * LC + row;
        const float* crow = Csrc + grow * DD + col;
        size_t xrow = grow * (size_t)(4 * DD);
        if (mode == 2)
            hsplit2_store(g_hXh, g_hXl, xrow + DD + col, v0, v1);
        int off = (mode == 2) ? 2 * DD : 3 * DD;
        hsplit2_store(g_hXh, g_hXl, xrow + off + col, crow[0] * v0, crow[1] * v1);
    } else {  // mode 4: final + bias (row is global over BB*LC; outF = harness out)
        *(float2*)(outF + (size_t)row * DD + col) =
            make_float2(v0 + bias[col], v1 + bias[col + 1]);
    }
}

// ======================= bf16x3 GEMM (S only) ===============================
#define KC 32
#define LDT 40                         // padded smem row stride (80 B)
#define PADB 80
#define TILEB (128 * PADB)             // 10240 B per matrix tile
#define STAGEB4 (4 * TILEB)            // Ah, Al, Bh, Bl = 40960 B
#define SMEM_G3 (2 * STAGEB4)          // 81920 B

__global__ void __launch_bounds__(256, 2)
wmma_gemm_b3(int aIdx, int bIdx, size_t aStride, size_t bStride, int K, int mode,
             float* __restrict__ outH,
             const float* __restrict__ Csrc, const float* __restrict__ bias) {
    extern __shared__ __align__(16) char dsm[];
    int tid = threadIdx.x, lane = tid & 31, wid = tid >> 5;
    int warp_m = wid & 1, warp_n = wid >> 1;
    int b = blockIdx.z;
    int row0 = blockIdx.y << 7, col0 = blockIdx.x << 7;

    const bf16* base[4];
    base[0] = bufH(aIdx) + (size_t)b * aStride + (size_t)row0 * K;
    base[1] = bufL(aIdx) + (size_t)b * aStride + (size_t)row0 * K;
    base[2] = bufH(bIdx) + (size_t)b * bStride + (size_t)col0 * K;
    base[3] = bufL(bIdx) + (size_t)b * bStride + (size_t)col0 * K;

    uint32_t sb = smem_u32(dsm);
    wmma::fragment<wmma::accumulator, 16, 16, 16, float> acc[4][2];
#pragma unroll
    for (int mi = 0; mi < 4; mi++)
#pragma unroll
        for (int nj = 0; nj < 2; nj++) wmma::fill_fragment(acc[mi][nj], 0.0f);

    const int KT = K / KC;
    int lrow = tid >> 1;
    int lcc0 = (tid & 1) << 1;

#define ISSUE4(kt, st) do {                                                    \
        int _k0 = (kt) * KC;                                                   \
        uint32_t _s0 = sb + (st) * STAGEB4;                                    \
        _Pragma("unroll")                                                      \
        for (int m = 0; m < 4; m++) {                                          \
            const bf16* _g = base[m] + (size_t)lrow * K + _k0;                 \
            uint32_t _sm = _s0 + m * TILEB + lrow * PADB;                      \
            CP_ASYNC(_sm + lcc0 * 16, _g + lcc0 * 8);                          \
            CP_ASYNC(_sm + (lcc0 + 1) * 16, _g + (lcc0 + 1) * 8);              \
        }                                                                      \
        CP_COMMIT();                                                           \
    } while (0)

    ISSUE4(0, 0);

    for (int kt = 0; kt < KT; kt++) {
        int st = kt & 1;
        if (kt + 1 < KT) {
            ISSUE4(kt + 1, st ^ 1);
            CP_WAIT(1);
        } else {
            CP_WAIT(0);
        }
        __syncthreads();

        const bf16* sAh = (const bf16*)(dsm + st * STAGEB4 + 0 * TILEB);
        const bf16* sAl = (const bf16*)(dsm + st * STAGEB4 + 1 * TILEB);
        const bf16* sBh = (const bf16*)(dsm + st * STAGEB4 + 2 * TILEB);
        const bf16* sBl = (const bf16*)(dsm + st * STAGEB4 + 3 * TILEB);

#pragma unroll
        for (int ks = 0; ks < KC; ks += 16) {
            wmma::fragment<wmma::matrix_b, 16, 16, 16, bf16, wmma::col_major> fbh[2], fbl[2];
#pragma unroll
            for (int nj = 0; nj < 2; nj++) {
                int nrow = warp_n * 32 + nj * 16;
                wmma::load_matrix_sync(fbh[nj], sBh + nrow * LDT + ks, LDT);
                wmma::load_matrix_sync(fbl[nj], sBl + nrow * LDT + ks, LDT);
            }
#pragma unroll
            for (int mi = 0; mi < 4; mi++) {
                int arow = warp_m * 64 + mi * 16;
                wmma::fragment<wmma::matrix_a, 16, 16, 16, bf16, wmma::row_major> fah, fal;
                wmma::load_matrix_sync(fah, sAh + arow * LDT + ks, LDT);
                wmma::load_matrix_sync(fal, sAl + arow * LDT + ks, LDT);
#pragma unroll
                for (int nj = 0; nj < 2; nj++) {
                    wmma::mma_sync(acc[mi][nj], fah, fbh[nj], acc[mi][nj]);
                    wmma::mma_sync(acc[mi][nj], fah, fbl[nj], acc[mi][nj]);
                    wmma::mma_sync(acc[mi][nj], fal, fbh[nj], acc[mi][nj]);
                }
            }
        }
        __syncthreads();
    }

    float* stag = reinterpret_cast<float*>(dsm) + wid * 256;
    int prow = lane >> 1, pc0 = (lane & 1) << 3;
#pragma unroll
    for (int mi = 0; mi < 4; mi++)
#pragma unroll
        for (int nj = 0; nj < 2; nj++) {
            wmma::store_matrix_sync(stag, acc[mi][nj], 16, wmma::mem_row_major);
            __syncwarp();
            int rr = row0 + warp_m * 64 + mi * 16 + prow;
            int cc0 = col0 + warp_n * 32 + nj * 16 + pc0;
#pragma unroll
            for (int p = 0; p < 8; p += 2)
                epi_pair(mode, b, rr, cc0 + p,
                         stag[prow * 16 + pc0 + p], stag[prow * 16 + pc0 + p + 1],
                         outH, Csrc, bias);
            __syncwarp();
        }
}

// ======================= fp16 2-pass GEMM (T, A, Bm, final) =================
#define STAGEB3 (3 * TILEB)            // Ah, Al, B = 30720 B
#define SMEM_G2 (2 * STAGEB3)          // 61440 B

__global__ void __launch_bounds__(256, 2)
wmma_gemm_h2(int aIdx, int bIdx, size_t aStride, size_t bStride, int K, int mode,
             float* __restrict__ outH,
             const float* __restrict__ Csrc, const float* __restrict__ bias) {
    extern __shared__ __align__(16) char dsm[];
    int tid = threadIdx.x, lane = tid & 31, wid = tid >> 5;
    int warp_m = wid & 1, warp_n = wid >> 1;
    int b = blockIdx.z;
    int row0 = blockIdx.y << 7, col0 = blockIdx.x << 7;

    const half* base[3];
    base[0] = habufH(aIdx) + (size_t)b * aStride + (size_t)row0 * K;
    base[1] = habufL(aIdx) + (size_t)b * aStride + (size_t)row0 * K;
    base[2] = hbbuf(bIdx) + (size_t)b * bStride + (size_t)col0 * K;

    uint32_t sb = smem_u32(dsm);
    wmma::fragment<wmma::accumulator, 16, 16, 16, float> acc[4][2];
#pragma unroll
    for (int mi = 0; mi < 4; mi++)
#pragma unroll
        for (int nj = 0; nj < 2; nj++) wmma::fill_fragment(acc[mi][nj], 0.0f);

    const int KT = K / KC;
    int lrow = tid >> 1;
    int lcc0 = (tid & 1) << 1;

#define ISSUE3(kt, st) do {                                                    \
        int _k0 = (kt) * KC;                                                   \
        uint32_t _s0 = sb + (st) * STAGEB3;                                    \
        _Pragma("unroll")                                                      \
        for (int m = 0; m < 3; m++) {                                          \
            const half* _g = base[m] + (size_t)lrow * K + _k0;                 \
            uint32_t _sm = _s0 + m * TILEB + lrow * PADB;                      \
            CP_ASYNC(_sm + lcc0 * 16, _g + lcc0 * 8);                          \
            CP_ASYNC(_sm + (lcc0 + 1) * 16, _g + (lcc0 + 1) * 8);              \
        }                                                                      \
        CP_COMMIT();                                                           \
    } while (0)

    ISSUE3(0, 0);

    for (int kt = 0; kt < KT; kt++) {
        int st = kt & 1;
        if (kt + 1 < KT) {
            ISSUE3(kt + 1, st ^ 1);
            CP_WAIT(1);
        } else {
            CP_WAIT(0);
        }
        __syncthreads();

        const half* sAh = (const half*)(dsm + st * STAGEB3 + 0 * TILEB);
        const half* sAl = (const half*)(dsm + st * STAGEB3 + 1 * TILEB);
        const half* sB  = (const half*)(dsm + st * STAGEB3 + 2 * TILEB);

#pragma unroll
        for (int ks = 0; ks < KC; ks += 16) {
            wmma::fragment<wmma::matrix_b, 16, 16, 16, half, wmma::col_major> fb[2];
#pragma unroll
            for (int nj = 0; nj < 2; nj++) {
                int nrow = warp_n * 32 + nj * 16;
                wmma::load_matrix_sync(fb[nj], sB + nrow * LDT + ks, LDT);
            }
#pragma unroll
            for (int mi = 0; mi < 4; mi++) {
                int arow = warp_m * 64 + mi * 16;
                wmma::fragment<wmma::matrix_a, 16, 16, 16, half, wmma::row_major> fah, fal;
                wmma::load_matrix_sync(fah, sAh + arow * LDT + ks, LDT);
                wmma::load_matrix_sync(fal, sAl + arow * LDT + ks, LDT);
#pragma unroll
                for (int nj = 0; nj < 2; nj++) {
                    wmma::mma_sync(acc[mi][nj], fah, fb[nj], acc[mi][nj]);
                    wmma::mma_sync(acc[mi][nj], fal, fb[nj], acc[mi][nj]);
                }
            }
        }
        __syncthreads();
    }

    float* stag = reinterpret_cast<float*>(dsm) + wid * 256;
    int prow = lane >> 1, pc0 = (lane & 1) << 3;
#pragma unroll
    for (int mi = 0; mi < 4; mi++)
#pragma unroll
        for (int nj = 0; nj < 2; nj++) {
            wmma::store_matrix_sync(stag, acc[mi][nj], 16, wmma::mem_row_major);
            __syncwarp();
            int rr = row0 + warp_m * 64 + mi * 16 + prow;
            int cc0 = col0 + warp_n * 32 + nj * 16 + pc0;
#pragma unroll
            for (int p = 0; p < 8; p += 2)
                epi_pair(mode, b, rr, cc0 + p,
                         stag[prow * 16 + pc0 + p], stag[prow * 16 + pc0 + p + 1],
                         outH, Csrc, bias);
            __syncwarp();
        }
}

// ======================= launch =============================================
extern "C" void kernel_launch(void* const* d_in, const int* in_sizes, int n_in,
                              void* d_out, int out_size) {
    const float* C     = (const float*)d_in[0];
    const float* Q     = (const float*)d_in[1];
    const float* cmask = (const float*)d_in[2];
    const float* qmask = (const float*)d_in[3];
    const float* w     = (const float*)d_in[4];
    const float* out_w = (const float*)d_in[5];
    const float* out_b = (const float*)d_in[6];
    float* out         = (float*)d_out;

    static int smem_set = 0;
    if (!smem_set) {
        cudaFuncSetAttribute(wmma_gemm_b3, cudaFuncAttributeMaxDynamicSharedMemorySize,
                             SMEM_G3);
        cudaFuncSetAttribute(wmma_gemm_h2, cudaFuncAttributeMaxDynamicSharedMemorySize,
                             SMEM_G2);
        smem_set = 1;
    }

    // row dots
    rowdot_kernel<<<(BB * LC) / 8, 256>>>(C, w, 0, BB * LC);
    rowdot_kernel<<<(BB * LQ) / 8, 256>>>(Q, w + DD, 1, BB * LQ);

    // operand prep
    {
        size_t n = (size_t)BB * LC * DD;
        split_c_kernel<<<(unsigned)(n / 1024), 256>>>(C, w + 2 * DD);
    }
    {
        size_t n = (size_t)BB * LQ * DD;
        split4_bf16_kernel<<<(unsigned)(n / 1024), 256>>>(Q, 1 /*Q*/, n);
    }
    {
        size_t n = (size_t)DD * 4 * DD;
        split4_h_kernel<<<(unsigned)(n / 1024), 256>>>(out_w, 3 /*W*/, n);
    }
    transpose_h_kernel<<<dim3(DD / 32, LQ / 32, BB), dim3(32, 8)>>>(Q, 0, 0 /*QT*/, 0, LQ, DD);
    transpose_h_kernel<<<dim3(DD / 32, LC / 32, BB), dim3(32, 8)>>>(C, 0, 1 /*CT*/, 0, LC, DD);

    // S = (C*w3) @ Q^T + c1 + q2  (bf16x3 precision)
    wmma_gemm_b3<<<dim3(LQ / 128, LC / 128, BB), 256, SMEM_G3>>>(
        0 /*CW*/, 1 /*Q*/, (size_t)LC * DD, (size_t)LQ * DD, DD, 0, nullptr, nullptr, nullptr);

    // softmaxes
    softmax_row_kernel<<<dim3(LC, BB), 256>>>(qmask);        // -> hS1 pair
    softmax_col_kernel<<<dim3(LQ / 256, BB), 256>>>(cmask);  // -> g_S2 fp32
    transpose_h_kernel<<<dim3(LQ / 32, LC / 32, BB), dim3(32, 8)>>>(nullptr, 1, 1 /*S2T*/, 1, LC, LQ);

    // T = S2^T @ C   (fp16 2-pass)
    wmma_gemm_h2<<<dim3(DD / 128, LQ / 128, BB), 256, SMEM_G2>>>(
        1 /*S2T*/, 1 /*CT*/, (size_t)LQ * LC, (size_t)DD * LC, LC, 1, nullptr, nullptr, nullptr);
    transpose_h_kernel<<<dim3(DD / 32, LQ / 32, BB), dim3(32, 8)>>>(nullptr, 2, 2 /*TT*/, 0, LQ, DD);

    // A = S1 @ Q  -> X[:,512:1024], C*A -> X[:,1024:1536]
    wmma_gemm_h2<<<dim3(DD / 128, LC / 128, BB), 256, SMEM_G2>>>(
        0 /*S1*/, 0 /*QT*/, (size_t)LC * LQ, (size_t)DD * LQ, LQ, 2, nullptr, C, nullptr);

    // Bm = S1 @ T -> C*Bm -> X[:,1536:2048]
    wmma_gemm_h2<<<dim3(DD / 128, LC / 128, BB), 256, SMEM_G2>>>(
        0 /*S1*/, 2 /*TT*/, (size_t)LC * LQ, (size_t)DD * LQ, LQ, 3, nullptr, C, nullptr);

    // out = X @ out_w^T + out_b
    wmma_gemm_h2<<<dim3(DD / 128, (BB * LC) / 128, 1), 256, SMEM_G2>>>(
        2 /*X*/, 3 /*W*/, 0, 0, 4 * DD, 4, out, nullptr, out_b);
}

// round 17
// speedup vs baseline: 2.4358x; 1.2514x over previous
#include <cuda_runtime.h>
#include <cuda_bf16.h>
#include <cuda_fp16.h>
#include <mma.h>
#include <stdint.h>
#include <math.h>

using namespace nvcuda;

#define BB 16
#define LC 1024
#define LQ 512
#define DD 512
#define NEG_INF_F (-1e30f)

typedef __nv_bfloat16 bf16;

// ======================= scratch (static device arrays) =====================
__device__ float g_c1[BB * LC];
__device__ float g_q2[BB * LQ];
__device__ float g_S [(size_t)BB * LC * LQ];   // logits
__device__ float g_S2[(size_t)BB * LC * LQ];   // col softmax fp32
__device__ float g_T [(size_t)BB * LQ * DD];   // S2^T C fp32

// bf16 pairs (S-GEMM operands only)
__device__ bf16 g_CWh[(size_t)BB * LC * DD], g_CWl[(size_t)BB * LC * DD];
__device__ bf16 g_Qh [(size_t)BB * LQ * DD], g_Ql [(size_t)BB * LQ * DD];

// fp16 singles for T/A/Bm/final GEMMs
__device__ half g_hQT[(size_t)BB * DD * LQ];
__device__ half g_hCT[(size_t)BB * DD * LC];
__device__ half g_hTT[(size_t)BB * DD * LQ];
__device__ half g_hW [(size_t)DD * 4 * DD];
__device__ half g_hS1[(size_t)BB * LC * LQ];
__device__ half g_hS2T[(size_t)BB * LQ * LC];
__device__ half g_hX [(size_t)BB * LC * 4 * DD];

// Device-side buffer resolution — NEVER pass __device__ symbols from host.
__device__ __forceinline__ bf16* bufH(int i) { return i ? g_Qh : g_CWh; }
__device__ __forceinline__ bf16* bufL(int i) { return i ? g_Ql : g_CWl; }
// fp16 singles: 0=QT 1=CT 2=TT 3=W 4=S1 5=S2T 6=X
__device__ __forceinline__ half* hbuf(int i) {
    switch (i) {
        case 0: return g_hQT; case 1: return g_hCT; case 2: return g_hTT;
        case 3: return g_hW;  case 4: return g_hS1; case 5: return g_hS2T;
        default: return g_hX;
    }
}

// ======================= helpers ============================================
__device__ __forceinline__ void bsplit(float x, bf16& h, bf16& l) {
    h = __float2bfloat16(x);
    l = __float2bfloat16(x - __bfloat162float(h));
}
#define CP_ASYNC(sa, ga) asm volatile( \
    "cp.async.cg.shared.global [%0], [%1], 16;" :: "r"(sa), "l"(ga))
#define CP_COMMIT() asm volatile("cp.async.commit_group;" ::: "memory")
#define CP_WAIT(n) asm volatile("cp.async.wait_group %0;" :: "n"(n) : "memory")
__device__ __forceinline__ uint32_t smem_u32(const void* p) {
    uint32_t a;
    asm("{ .reg .u64 t; cvta.to.shared.u64 t, %1; cvt.u32.u64 %0, t; }"
        : "=r"(a) : "l"(p));
    return a;
}

// ======================= small kernels ======================================
__global__ void rowdot_kernel(const float* __restrict__ X, const float* __restrict__ w,
                              int which, int nrows) {
    float* out = which ? g_q2 : g_c1;
    int gw = (blockIdx.x * blockDim.x + threadIdx.x) >> 5;
    int lane = threadIdx.x & 31;
    if (gw >= nrows) return;
    const float* row = X + (size_t)gw * DD;
    float s = 0.f;
#pragma unroll 4
    for (int k = lane; k < DD; k += 32) s = fmaf(row[k], w[k], s);
#pragma unroll
    for (int o = 16; o; o >>= 1) s += __shfl_xor_sync(0xffffffffu, s, o);
    if (lane == 0) out[gw] = s;
}

__device__ __forceinline__ void bsplit2_store(bf16* h, bf16* l, size_t idx,
                                              float a, float b) {
    bf16 h0, l0, h1, l1;
    bsplit(a, h0, l0);
    bsplit(b, h1, l1);
    *(__nv_bfloat162*)(h + idx) = __halves2bfloat162(h0, h1);
    *(__nv_bfloat162*)(l + idx) = __halves2bfloat162(l0, l1);
}
__device__ __forceinline__ void h2_store(half* d, size_t idx, float a, float b) {
    *(__half2*)(d + idx) = __halves2half2(__float2half(a), __float2half(b));
}

// C: one read -> CW bf16 pair (scaled) AND X[:,0:512] fp16
__global__ void split_c_kernel(const float* __restrict__ C, const float* __restrict__ w3) {
    size_t i = ((size_t)blockIdx.x * blockDim.x + threadIdx.x) * 4;  // < BB*LC*DD
    size_t row = i >> 9;
    int c = (int)(i & (DD - 1));
    float4 v = *(const float4*)(C + i);
    float4 s = *(const float4*)(w3 + c);
    h2_store(g_hX, row * (4 * DD) + c, v.x, v.y);
    h2_store(g_hX, row * (4 * DD) + c + 2, v.z, v.w);
    bsplit2_store(g_CWh, g_CWl, i, v.x * s.x, v.y * s.y);
    bsplit2_store(g_CWh, g_CWl, i + 2, v.z * s.z, v.w * s.w);
}

// fp32 -> bf16 pair (Q for S-GEMM)
__global__ void split4_bf16_kernel(const float* __restrict__ src, int dstIdx, size_t n) {
    size_t i = ((size_t)blockIdx.x * blockDim.x + threadIdx.x) * 4;
    if (i >= n) return;
    float4 v = *(const float4*)(src + i);
    bf16* h = bufH(dstIdx);
    bf16* l = bufL(dstIdx);
    bsplit2_store(h, l, i, v.x, v.y);
    bsplit2_store(h, l, i + 2, v.z, v.w);
}

// fp32 -> single fp16 (W)
__global__ void split4_h_kernel(const float* __restrict__ src, int dstIdx, size_t n) {
    size_t i = ((size_t)blockIdx.x * blockDim.x + threadIdx.x) * 4;
    if (i >= n) return;
    float4 v = *(const float4*)(src + i);
    half* d = hbuf(dstIdx);
    h2_store(d, i, v.x, v.y);
    h2_store(d, i + 2, v.z, v.w);
}

// src fp32 [R x Cc] per batch -> fp16 transposed [Cc x R].
// srcSel: 0 = srcParam, 1 = g_S2, 2 = g_T
__global__ void transpose_h_kernel(const float* __restrict__ srcParam, int srcSel,
                                   int dstIdx, int R, int Cc) {
    __shared__ float t[32][33];
    const float* src = (srcSel == 0) ? srcParam : (srcSel == 1 ? g_S2 : g_T);
    half* d = hbuf(dstIdx);
    int b = blockIdx.z;
    const float* S = src + (size_t)b * R * Cc;
    size_t ob = (size_t)b * R * Cc;
    int c0 = blockIdx.x * 32, r0 = blockIdx.y * 32;
    int tx = threadIdx.x, ty = threadIdx.y;
#pragma unroll
    for (int j = 0; j < 32; j += 8)
        t[ty + j][tx] = S[(size_t)(r0 + ty + j) * Cc + c0 + tx];
    __syncthreads();
#pragma unroll
    for (int j = 0; j < 32; j += 8) {
        float v = t[tx][ty + j];
        size_t o = ob + (size_t)(c0 + ty + j) * R + r0 + tx;
        d[o] = __float2half(v);
    }
}

__global__ void softmax_row_kernel(const float* __restrict__ qmask) {
    __shared__ float sred[64];
    int i = blockIdx.x, b = blockIdx.y;
    int t = threadIdx.x;
    size_t base = ((size_t)b * LC + i) * LQ;
    const float* srow = g_S + base;
    float m0 = qmask[b * LQ + t], m1 = qmask[b * LQ + t + 256];
    float x0 = srow[t] * m0 + (1.f - m0) * NEG_INF_F;
    float x1 = srow[t + 256] * m1 + (1.f - m1) * NEG_INF_F;
    float v = fmaxf(x0, x1);
    int lane = t & 31, wid = t >> 5;
#pragma unroll
    for (int o = 16; o; o >>= 1) v = fmaxf(v, __shfl_xor_sync(0xffffffffu, v, o));
    if (lane == 0) sred[wid] = v;
    __syncthreads();
    if (t < 32) {
        float w2 = (t < 8) ? sred[t] : -3e38f;
#pragma unroll
        for (int o = 4; o; o >>= 1) w2 = fmaxf(w2, __shfl_xor_sync(0xffffffffu, w2, o));
        if (t == 0) sred[32] = w2;
    }
    __syncthreads();
    float mx = sred[32];
    float e0 = __expf(x0 - mx), e1 = __expf(x1 - mx);
    v = e0 + e1;
#pragma unroll
    for (int o = 16; o; o >>= 1) v += __shfl_xor_sync(0xffffffffu, v, o);
    if (lane == 0) sred[wid] = v;
    __syncthreads();
    if (t < 32) {
        float w2 = (t < 8) ? sred[t] : 0.f;
#pragma unroll
        for (int o = 4; o; o >>= 1) w2 += __shfl_xor_sync(0xffffffffu, w2, o);
        if (t == 0) sred[33] = w2;
    }
    __syncthreads();
    float inv = 1.f / sred[33];
    g_hS1[base + t] = __float2half(e0 * inv);
    g_hS1[base + t + 256] = __float2half(e1 * inv);
}

__global__ void softmax_col_kernel(const float* __restrict__ cmask) {
    int j = blockIdx.x * blockDim.x + threadIdx.x;
    int b = blockIdx.y;
    const float* Sb = g_S + (size_t)b * LC * LQ;
    float* Ob = g_S2 + (size_t)b * LC * LQ;
    const float* cm = cmask + b * LC;
    float m = -3e38f, l = 0.f;
    for (int i = 0; i < LC; i++) {
        float cmi = cm[i];
        float x = Sb[(size_t)i * LQ + j] * cmi + (1.f - cmi) * NEG_INF_F;
        float nm = fmaxf(m, x);
        l = l * __expf(m - nm) + __expf(x - nm);
        m = nm;
    }
    float inv = 1.f / l;
    for (int i = 0; i < LC; i++) {
        float cmi = cm[i];
        float x = Sb[(size_t)i * LQ + j] * cmi + (1.f - cmi) * NEG_INF_F;
        Ob[(size_t)i * LQ + j] = __expf(x - m) * inv;
    }
}

// ======================= shared epilogue ====================================
__device__ __forceinline__ void epi_pair(int mode, int b, int row, int col,
                                         float v0, float v1, float* outF,
                                         const float* Csrc, const float* bias) {
    if (mode == 0) {  // S logits += c1[row] + q2[col]
        size_t grow = (size_t)b * LC + row;
        float c1v = g_c1[b * LC + row];
        float2 o = make_float2(v0 + c1v + g_q2[b * LQ + col],
                               v1 + c1v + g_q2[b * LQ + col + 1]);
        *(float2*)(g_S + grow * LQ + col) = o;
    } else if (mode == 1) {  // plain fp32 (T)
        *(float2*)(g_T + ((size_t)b * LQ + row) * DD + col) = make_float2(v0, v1);
    } else if (mode == 2 || mode == 3) {  // X features fp16
        size_t grow = (size_t)b * LC + row;
        const float* crow = Csrc + grow * DD + col;
        size_t xrow = grow * (size_t)(4 * DD);
        if (mode == 2)
            h2_store(g_hX, xrow + DD + col, v0, v1);
        int off = (mode == 2) ? 2 * DD : 3 * DD;
        h2_store(g_hX, xrow + off + col, crow[0] * v0, crow[1] * v1);
    } else {  // mode 4: final + bias (row is global over BB*LC; outF = harness out)
        *(float2*)(outF + (size_t)row * DD + col) =
            make_float2(v0 + bias[col], v1 + bias[col + 1]);
    }
}

// ======================= bf16x3 GEMM (S only) ===============================
#define KC 32
#define LDT 40                         // padded smem row stride (80 B)
#define PADB 80
#define TILEB (128 * PADB)             // 10240 B per matrix tile
#define STAGEB4 (4 * TILEB)            // Ah, Al, Bh, Bl = 40960 B
#define SMEM_G3 (2 * STAGEB4)          // 81920 B

__global__ void __launch_bounds__(256, 2)
wmma_gemm_b3(int aIdx, int bIdx, size_t aStride, size_t bStride, int K, int mode,
             float* __restrict__ outH,
             const float* __restrict__ Csrc, const float* __restrict__ bias) {
    extern __shared__ __align__(16) char dsm[];
    int tid = threadIdx.x, lane = tid & 31, wid = tid >> 5;
    int warp_m = wid & 1, warp_n = wid >> 1;
    int b = blockIdx.z;
    int row0 = blockIdx.y << 7, col0 = blockIdx.x << 7;

    const bf16* base[4];
    base[0] = bufH(aIdx) + (size_t)b * aStride + (size_t)row0 * K;
    base[1] = bufL(aIdx) + (size_t)b * aStride + (size_t)row0 * K;
    base[2] = bufH(bIdx) + (size_t)b * bStride + (size_t)col0 * K;
    base[3] = bufL(bIdx) + (size_t)b * bStride + (size_t)col0 * K;

    uint32_t sb = smem_u32(dsm);
    wmma::fragment<wmma::accumulator, 16, 16, 16, float> acc[4][2];
#pragma unroll
    for (int mi = 0; mi < 4; mi++)
#pragma unroll
        for (int nj = 0; nj < 2; nj++) wmma::fill_fragment(acc[mi][nj], 0.0f);

    const int KT = K / KC;
    int lrow = tid >> 1;
    int lcc0 = (tid & 1) << 1;

#define ISSUE4(kt, st) do {                                                    \
        int _k0 = (kt) * KC;                                                   \
        uint32_t _s0 = sb + (st) * STAGEB4;                                    \
        _Pragma("unroll")                                                      \
        for (int m = 0; m < 4; m++) {                                          \
            const bf16* _g = base[m] + (size_t)lrow * K + _k0;                 \
            uint32_t _sm = _s0 + m * TILEB + lrow * PADB;                      \
            CP_ASYNC(_sm + lcc0 * 16, _g + lcc0 * 8);                          \
            CP_ASYNC(_sm + (lcc0 + 1) * 16, _g + (lcc0 + 1) * 8);              \
        }                                                                      \
        CP_COMMIT();                                                           \
    } while (0)

    ISSUE4(0, 0);

    for (int kt = 0; kt < KT; kt++) {
        int st = kt & 1;
        if (kt + 1 < KT) {
            ISSUE4(kt + 1, st ^ 1);
            CP_WAIT(1);
        } else {
            CP_WAIT(0);
        }
        __syncthreads();

        const bf16* sAh = (const bf16*)(dsm + st * STAGEB4 + 0 * TILEB);
        const bf16* sAl = (const bf16*)(dsm + st * STAGEB4 + 1 * TILEB);
        const bf16* sBh = (const bf16*)(dsm + st * STAGEB4 + 2 * TILEB);
        const bf16* sBl = (const bf16*)(dsm + st * STAGEB4 + 3 * TILEB);

#pragma unroll
        for (int ks = 0; ks < KC; ks += 16) {
            wmma::fragment<wmma::matrix_b, 16, 16, 16, bf16, wmma::col_major> fbh[2], fbl[2];
#pragma unroll
            for (int nj = 0; nj < 2; nj++) {
                int nrow = warp_n * 32 + nj * 16;
                wmma::load_matrix_sync(fbh[nj], sBh + nrow * LDT + ks, LDT);
                wmma::load_matrix_sync(fbl[nj], sBl + nrow * LDT + ks, LDT);
            }
#pragma unroll
            for (int mi = 0; mi < 4; mi++) {
                int arow = warp_m * 64 + mi * 16;
                wmma::fragment<wmma::matrix_a, 16, 16, 16, bf16, wmma::row_major> fah, fal;
                wmma::load_matrix_sync(fah, sAh + arow * LDT + ks, LDT);
                wmma::load_matrix_sync(fal, sAl + arow * LDT + ks, LDT);
#pragma unroll
                for (int nj = 0; nj < 2; nj++) {
                    wmma::mma_sync(acc[mi][nj], fah, fbh[nj], acc[mi][nj]);
                    wmma::mma_sync(acc[mi][nj], fah, fbl[nj], acc[mi][nj]);
                    wmma::mma_sync(acc[mi][nj], fal, fbh[nj], acc[mi][nj]);
                }
            }
        }
        __syncthreads();
    }

    float* stag = reinterpret_cast<float*>(dsm) + wid * 256;
    int prow = lane >> 1, pc0 = (lane & 1) << 3;
#pragma unroll
    for (int mi = 0; mi < 4; mi++)
#pragma unroll
        for (int nj = 0; nj < 2; nj++) {
            wmma::store_matrix_sync(stag, acc[mi][nj], 16, wmma::mem_row_major);
            __syncwarp();
            int rr = row0 + warp_m * 64 + mi * 16 + prow;
            int cc0 = col0 + warp_n * 32 + nj * 16 + pc0;
#pragma unroll
            for (int p = 0; p < 8; p += 2)
                epi_pair(mode, b, rr, cc0 + p,
                         stag[prow * 16 + pc0 + p], stag[prow * 16 + pc0 + p + 1],
                         outH, Csrc, bias);
            __syncwarp();
        }
}

// ======================= fp16 1-pass GEMM (T, A, Bm, final) =================
#define STAGEB2 (2 * TILEB)            // A, B = 20480 B
#define SMEM_G1 (2 * STAGEB2)          // 40960 B

__global__ void __launch_bounds__(256, 2)
wmma_gemm_h1(int aIdx, int bIdx, size_t aStride, size_t bStride, int K, int mode,
             float* __restrict__ outH,
             const float* __restrict__ Csrc, const float* __restrict__ bias) {
    extern __shared__ __align__(16) char dsm[];
    int tid = threadIdx.x, lane = tid & 31, wid = tid >> 5;
    int warp_m = wid & 1, warp_n = wid >> 1;
    int b = blockIdx.z;
    int row0 = blockIdx.y << 7, col0 = blockIdx.x << 7;

    const half* base[2];
    base[0] = hbuf(aIdx) + (size_t)b * aStride + (size_t)row0 * K;
    base[1] = hbuf(bIdx) + (size_t)b * bStride + (size_t)col0 * K;

    uint32_t sb = smem_u32(dsm);
    wmma::fragment<wmma::accumulator, 16, 16, 16, float> acc[4][2];
#pragma unroll
    for (int mi = 0; mi < 4; mi++)
#pragma unroll
        for (int nj = 0; nj < 2; nj++) wmma::fill_fragment(acc[mi][nj], 0.0f);

    const int KT = K / KC;
    int lrow = tid >> 1;
    int lcc0 = (tid & 1) << 1;

#define ISSUE2(kt, st) do {                                                    \
        int _k0 = (kt) * KC;                                                   \
        uint32_t _s0 = sb + (st) * STAGEB2;                                    \
        _Pragma("unroll")                                                      \
        for (int m = 0; m < 2; m++) {                                          \
            const half* _g = base[m] + (size_t)lrow * K + _k0;                 \
            uint32_t _sm = _s0 + m * TILEB + lrow * PADB;                      \
            CP_ASYNC(_sm + lcc0 * 16, _g + lcc0 * 8);                          \
            CP_ASYNC(_sm + (lcc0 + 1) * 16, _g + (lcc0 + 1) * 8);              \
        }                                                                      \
        CP_COMMIT();                                                           \
    } while (0)

    ISSUE2(0, 0);

    for (int kt = 0; kt < KT; kt++) {
        int st = kt & 1;
        if (kt + 1 < KT) {
            ISSUE2(kt + 1, st ^ 1);
            CP_WAIT(1);
        } else {
            CP_WAIT(0);
        }
        __syncthreads();

        const half* sA = (const half*)(dsm + st * STAGEB2 + 0 * TILEB);
        const half* sB = (const half*)(dsm + st * STAGEB2 + 1 * TILEB);

#pragma unroll
        for (int ks = 0; ks < KC; ks += 16) {
            wmma::fragment<wmma::matrix_b, 16, 16, 16, half, wmma::col_major> fb[2];
#pragma unroll
            for (int nj = 0; nj < 2; nj++) {
                int nrow = warp_n * 32 + nj * 16;
                wmma::load_matrix_sync(fb[nj], sB + nrow * LDT + ks, LDT);
            }
#pragma unroll
            for (int mi = 0; mi < 4; mi++) {
                int arow = warp_m * 64 + mi * 16;
                wmma::fragment<wmma::matrix_a, 16, 16, 16, half, wmma::row_major> fa;
                wmma::load_matrix_sync(fa, sA + arow * LDT + ks, LDT);
#pragma unroll
                for (int nj = 0; nj < 2; nj++)
                    wmma::mma_sync(acc[mi][nj], fa, fb[nj], acc[mi][nj]);
            }
        }
        __syncthreads();
    }

    float* stag = reinterpret_cast<float*>(dsm) + wid * 256;
    int prow = lane >> 1, pc0 = (lane & 1) << 3;
#pragma unroll
    for (int mi = 0; mi < 4; mi++)
#pragma unroll
        for (int nj = 0; nj < 2; nj++) {
            wmma::store_matrix_sync(stag, acc[mi][nj], 16, wmma::mem_row_major);
            __syncwarp();
            int rr = row0 + warp_m * 64 + mi * 16 + prow;
            int cc0 = col0 + warp_n * 32 + nj * 16 + pc0;
#pragma unroll
            for (int p = 0; p < 8; p += 2)
                epi_pair(mode, b, rr, cc0 + p,
                         stag[prow * 16 + pc0 + p], stag[prow * 16 + pc0 + p + 1],
                         outH, Csrc, bias);
            __syncwarp();
        }
}

// ======================= launch =============================================
extern "C" void kernel_launch(void* const* d_in, const int* in_sizes, int n_in,
                              void* d_out, int out_size) {
    const float* C     = (const float*)d_in[0];
    const float* Q     = (const float*)d_in[1];
    const float* cmask = (const float*)d_in[2];
    const float* qmask = (const float*)d_in[3];
    const float* w     = (const float*)d_in[4];
    const float* out_w = (const float*)d_in[5];
    const float* out_b = (const float*)d_in[6];
    float* out         = (float*)d_out;

    static int smem_set = 0;
    if (!smem_set) {
        cudaFuncSetAttribute(wmma_gemm_b3, cudaFuncAttributeMaxDynamicSharedMemorySize,
                             SMEM_G3);
        cudaFuncSetAttribute(wmma_gemm_h1, cudaFuncAttributeMaxDynamicSharedMemorySize,
                             SMEM_G1);
        smem_set = 1;
    }

    // row dots
    rowdot_kernel<<<(BB * LC) / 8, 256>>>(C, w, 0, BB * LC);
    rowdot_kernel<<<(BB * LQ) / 8, 256>>>(Q, w + DD, 1, BB * LQ);

    // operand prep
    {
        size_t n = (size_t)BB * LC * DD;
        split_c_kernel<<<(unsigned)(n / 1024), 256>>>(C, w + 2 * DD);
    }
    {
        size_t n = (size_t)BB * LQ * DD;
        split4_bf16_kernel<<<(unsigned)(n / 1024), 256>>>(Q, 1 /*Q*/, n);
    }
    {
        size_t n = (size_t)DD * 4 * DD;
        split4_h_kernel<<<(unsigned)(n / 1024), 256>>>(out_w, 3 /*W*/, n);
    }
    transpose_h_kernel<<<dim3(DD / 32, LQ / 32, BB), dim3(32, 8)>>>(Q, 0, 0 /*QT*/, LQ, DD);
    transpose_h_kernel<<<dim3(DD / 32, LC / 32, BB), dim3(32, 8)>>>(C, 0, 1 /*CT*/, LC, DD);

    // S = (C*w3) @ Q^T + c1 + q2  (bf16x3 precision)
    wmma_gemm_b3<<<dim3(LQ / 128, LC / 128, BB), 256, SMEM_G3>>>(
        0 /*CW*/, 1 /*Q*/, (size_t)LC * DD, (size_t)LQ * DD, DD, 0, nullptr, nullptr, nullptr);

    // softmaxes
    softmax_row_kernel<<<dim3(LC, BB), 256>>>(qmask);        // -> g_hS1
    softmax_col_kernel<<<dim3(LQ / 256, BB), 256>>>(cmask);  // -> g_S2 fp32
    transpose_h_kernel<<<dim3(LQ / 32, LC / 32, BB), dim3(32, 8)>>>(nullptr, 1, 5 /*S2T*/, LC, LQ);

    // T = S2^T @ C   (fp16 1-pass)
    wmma_gemm_h1<<<dim3(DD / 128, LQ / 128, BB), 256, SMEM_G1>>>(
        5 /*S2T*/, 1 /*CT*/, (size_t)LQ * LC, (size_t)DD * LC, LC, 1, nullptr, nullptr, nullptr);
    transpose_h_kernel<<<dim3(DD / 32, LQ / 32, BB), dim3(32, 8)>>>(nullptr, 2, 2 /*TT*/, LQ, DD);

    // A = S1 @ Q  -> X[:,512:1024], C*A -> X[:,1024:1536]
    wmma_gemm_h1<<<dim3(DD / 128, LC / 128, BB), 256, SMEM_G1>>>(
        4 /*S1*/, 0 /*QT*/, (size_t)LC * LQ, (size_t)DD * LQ, LQ, 2, nullptr, C, nullptr);

    // Bm = S1 @ T -> C*Bm -> X[:,1536:2048]
    wmma_gemm_h1<<<dim3(DD / 128, LC / 128, BB), 256, SMEM_G1>>>(
        4 /*S1*/, 2 /*TT*/, (size_t)LC * LQ, (size_t)DD * LQ, LQ, 3, nullptr, C, nullptr);

    // out = X @ out_w^T + out_b
    wmma_gemm_h1<<<dim3(DD / 128, (BB * LC) / 128, 1), 256, SMEM_G1>>>(
        6 /*X*/, 3 /*W*/, 0, 0, 4 * DD, 4, out, nullptr, out_b);
}